// round 1
// baseline (speedup 1.0000x reference)
#include <cuda_runtime.h>
#include <math.h>
#include <float.h>

// Problem constants (fixed shapes from reference)
#define BB   16
#define CC   512
#define TT   4096
#define EE   256
#define KK   1024
#define NN   (BB * TT)   // 65536

// Scratch (device globals -- no allocation allowed)
__device__ float        g_y[NN * EE];     // projected features, row-major (n, e)
__device__ int          g_idx[NN];        // argmin code per position
__device__ float        g_e2[KK];         // ||embed_k||^2
__device__ unsigned int g_hist[KK];       // code histogram
__device__ double       g_loss;           // sum of squared commitment diffs

// ---------------------------------------------------------------------------
// Init: zero accumulators, compute ||e_k||^2
// ---------------------------------------------------------------------------
__global__ void init_kernel(const float* __restrict__ embed) {
    int k = blockIdx.x * blockDim.x + threadIdx.x;  // 0..1023
    if (k < KK) {
        const float* row = embed + (size_t)k * EE;
        float s = 0.f;
#pragma unroll 8
        for (int e = 0; e < EE; e++) {
            float v = row[e];
            s += v * v;
        }
        g_e2[k] = s;
        g_hist[k] = 0u;
    }
    if (k == 0) g_loss = 0.0;
}

// ---------------------------------------------------------------------------
// Projection GEMM: y[n, e] = sum_c x[b, c, t] * w[e, c] + bias[e]
// Tiles: 64 (t) x 64 (e) x 16 (c). Block 16x16, 4x4 per thread.
// ---------------------------------------------------------------------------
__global__ void proj_kernel(const float* __restrict__ x,
                            const float* __restrict__ w,
                            const float* __restrict__ bias) {
    __shared__ float As[16][64];  // As[c][t]
    __shared__ float Bs[16][64];  // Bs[c][e]

    const int b  = blockIdx.z;
    const int t0 = blockIdx.x * 64;
    const int e0 = blockIdx.y * 64;
    const int tx = threadIdx.x, ty = threadIdx.y;
    const int tid = ty * 16 + tx;

    float acc[4][4] = {};

    const int ka = tid >> 4;          // 0..15  (c within tile)
    const int ma = (tid & 15) * 4;    // t offset
    const int er = tid >> 2;          // 0..63  (e row)
    const int cb = (tid & 3) * 4;     // c offset

    for (int c0 = 0; c0 < CC; c0 += 16) {
        // load x tile (coalesced along t)
        const float4 xv = *(const float4*)(x + ((size_t)(b * CC + c0 + ka)) * TT + t0 + ma);
        *(float4*)&As[ka][ma] = xv;
        // load w tile (coalesced along c), transpose into Bs[c][e]
        const float4 wv = *(const float4*)(w + (size_t)(e0 + er) * CC + c0 + cb);
        Bs[cb + 0][er] = wv.x;
        Bs[cb + 1][er] = wv.y;
        Bs[cb + 2][er] = wv.z;
        Bs[cb + 3][er] = wv.w;
        __syncthreads();

#pragma unroll
        for (int k2 = 0; k2 < 16; k2++) {
            float4 a = *(const float4*)&As[k2][ty * 4];
            float4 bq = *(const float4*)&Bs[k2][tx * 4];
            acc[0][0] += a.x * bq.x; acc[0][1] += a.x * bq.y; acc[0][2] += a.x * bq.z; acc[0][3] += a.x * bq.w;
            acc[1][0] += a.y * bq.x; acc[1][1] += a.y * bq.y; acc[1][2] += a.y * bq.z; acc[1][3] += a.y * bq.w;
            acc[2][0] += a.z * bq.x; acc[2][1] += a.z * bq.y; acc[2][2] += a.z * bq.z; acc[2][3] += a.z * bq.w;
            acc[3][0] += a.w * bq.x; acc[3][1] += a.w * bq.y; acc[3][2] += a.w * bq.z; acc[3][3] += a.w * bq.w;
        }
        __syncthreads();
    }

    const float4 bv = *(const float4*)(bias + e0 + tx * 4);
#pragma unroll
    for (int i = 0; i < 4; i++) {
        const int n = b * TT + t0 + ty * 4 + i;
        float4 o;
        o.x = acc[i][0] + bv.x;
        o.y = acc[i][1] + bv.y;
        o.z = acc[i][2] + bv.z;
        o.w = acc[i][3] + bv.w;
        *(float4*)&g_y[(size_t)n * EE + e0 + tx * 4] = o;
    }
}

// ---------------------------------------------------------------------------
// Distance GEMM + argmin: for each n, idx = argmin_k ( ||e_k||^2 - 2 y_n.e_k )
// Block handles 64 n's; loops over all K=1024 codes in 64-wide tiles.
// ---------------------------------------------------------------------------
__global__ void argmin_kernel(const float* __restrict__ embed) {
    __shared__ float Ys[16][64];   // Ys[e][n]
    __shared__ float Es[16][64];   // Es[e][k]
    __shared__ float sE2[64];
    __shared__ float rVal[64][16];
    __shared__ int   rIdx[64][16];

    const int n0 = blockIdx.x * 64;
    const int tx = threadIdx.x, ty = threadIdx.y;
    const int tid = ty * 16 + tx;

    const int rr = tid >> 2;          // 0..63 (row: n or k)
    const int eb = (tid & 3) * 4;     // e offset

    float bestv[4];
    int   besti[4];
#pragma unroll
    for (int i = 0; i < 4; i++) { bestv[i] = FLT_MAX; besti[i] = 0; }

    for (int k0 = 0; k0 < KK; k0 += 64) {
        __syncthreads();              // protect sE2 / smem reuse across k0 iters
        if (tid < 64) sE2[tid] = g_e2[k0 + tid];

        float acc[4][4] = {};
        for (int e0 = 0; e0 < EE; e0 += 16) {
            const float4 yv = *(const float4*)&g_y[(size_t)(n0 + rr) * EE + e0 + eb];
            Ys[eb + 0][rr] = yv.x; Ys[eb + 1][rr] = yv.y;
            Ys[eb + 2][rr] = yv.z; Ys[eb + 3][rr] = yv.w;
            const float4 ev = *(const float4*)(embed + (size_t)(k0 + rr) * EE + e0 + eb);
            Es[eb + 0][rr] = ev.x; Es[eb + 1][rr] = ev.y;
            Es[eb + 2][rr] = ev.z; Es[eb + 3][rr] = ev.w;
            __syncthreads();
#pragma unroll
            for (int k2 = 0; k2 < 16; k2++) {
                float4 a = *(const float4*)&Ys[k2][ty * 4];
                float4 bq = *(const float4*)&Es[k2][tx * 4];
                acc[0][0] += a.x * bq.x; acc[0][1] += a.x * bq.y; acc[0][2] += a.x * bq.z; acc[0][3] += a.x * bq.w;
                acc[1][0] += a.y * bq.x; acc[1][1] += a.y * bq.y; acc[1][2] += a.y * bq.z; acc[1][3] += a.y * bq.w;
                acc[2][0] += a.z * bq.x; acc[2][1] += a.z * bq.y; acc[2][2] += a.z * bq.z; acc[2][3] += a.z * bq.w;
                acc[3][0] += a.w * bq.x; acc[3][1] += a.w * bq.y; acc[3][2] += a.w * bq.z; acc[3][3] += a.w * bq.w;
            }
            __syncthreads();
        }

#pragma unroll
        for (int i = 0; i < 4; i++) {
#pragma unroll
            for (int j = 0; j < 4; j++) {
                const int k = k0 + tx * 4 + j;
                const float d = sE2[tx * 4 + j] - 2.0f * acc[i][j];
                if (d < bestv[i]) { bestv[i] = d; besti[i] = k; }
            }
        }
    }

    __syncthreads();
#pragma unroll
    for (int i = 0; i < 4; i++) {
        rVal[ty * 4 + i][tx] = bestv[i];
        rIdx[ty * 4 + i][tx] = besti[i];
    }
    __syncthreads();
    if (tid < 64) {
        float v = rVal[tid][0];
        int   ix = rIdx[tid][0];
#pragma unroll
        for (int j = 1; j < 16; j++) {
            float vj = rVal[tid][j];
            int ij = rIdx[tid][j];
            if (vj < v || (vj == v && ij < ix)) { v = vj; ix = ij; }
        }
        g_idx[n0 + tid] = ix;
    }
}

// ---------------------------------------------------------------------------
// Loss + histogram: block per position n, thread per e.
// ---------------------------------------------------------------------------
__global__ void loss_kernel(const float* __restrict__ embed) {
    __shared__ float red[8];
    const int n = blockIdx.x;
    const int e = threadIdx.x;
    const int idx = g_idx[n];
    const float zq = embed[(size_t)idx * EE + e];
    const float yv = g_y[(size_t)n * EE + e];
    const float d = zq - yv;
    float s = d * d;
    // warp reduce
#pragma unroll
    for (int off = 16; off > 0; off >>= 1)
        s += __shfl_down_sync(0xFFFFFFFFu, s, off);
    if ((e & 31) == 0) red[e >> 5] = s;
    __syncthreads();
    if (e == 0) {
        float tot = 0.f;
#pragma unroll
        for (int wgi = 0; wgi < 8; wgi++) tot += red[wgi];
        atomicAdd(&g_loss, (double)tot);
        atomicAdd(&g_hist[idx], 1u);
    }
}

// ---------------------------------------------------------------------------
// Transposed output: out[b, e, t] = embed[idx[b*T + t], e]
// ---------------------------------------------------------------------------
__global__ void out_kernel(const float* __restrict__ embed, float* __restrict__ out) {
    const int t = blockIdx.x * 256 + threadIdx.x;
    const int e = blockIdx.y;
    const int b = blockIdx.z;
    const int idx = g_idx[b * TT + t];
    out[((size_t)(b * EE + e)) * TT + t] = embed[(size_t)idx * EE + e];
}

// ---------------------------------------------------------------------------
// Finalize scalars: loss, kldiv_r (B entries), log_perplexity
// ---------------------------------------------------------------------------
__global__ void finalize_kernel(float* __restrict__ out, int out_size) {
    __shared__ float red[8];
    const int tid = threadIdx.x;  // 256 threads
    float s = 0.f;
    for (int k = tid; k < KK; k += 256) {
        float p = (float)g_hist[k] / (float)NN;
        s += p * logf(p + 1e-10f);
    }
#pragma unroll
    for (int off = 16; off > 0; off >>= 1)
        s += __shfl_down_sync(0xFFFFFFFFu, s, off);
    if ((tid & 31) == 0) red[tid >> 5] = s;
    __syncthreads();
    if (tid == 0) {
        float tot = 0.f;
#pragma unroll
        for (int wgi = 0; wgi < 8; wgi++) tot += red[wgi];
        const float log_perp = -tot;
        const float loss = 0.25f * (float)(g_loss / ((double)NN * (double)EE));
        const float kld = logf((float)KK) * (float)TT;  // log(1024) * 4096
        const long long base = (long long)NN * EE;      // 16777216
        if (base + 0 < out_size) out[base + 0] = loss;
        for (int i = 0; i < BB; i++)
            if (base + 1 + i < out_size) out[base + 1 + i] = kld;
        if (base + 1 + BB < out_size) out[base + 1 + BB] = log_perp;
    }
}

// ---------------------------------------------------------------------------
extern "C" void kernel_launch(void* const* d_in, const int* in_sizes, int n_in,
                              void* d_out, int out_size) {
    const float* x     = (const float*)d_in[0];  // (16, 512, 4096)
    const float* w     = (const float*)d_in[1];  // (256, 512)
    const float* bias  = (const float*)d_in[2];  // (256,)
    const float* embed = (const float*)d_in[3];  // (1024, 256)
    float* out = (float*)d_out;

    init_kernel<<<4, 256>>>(embed);
    dim3 blk(16, 16);
    proj_kernel<<<dim3(TT / 64, EE / 64, BB), blk>>>(x, w, bias);
    argmin_kernel<<<NN / 64, blk>>>(embed);
    loss_kernel<<<NN, 256>>>(embed);
    out_kernel<<<dim3(TT / 256, EE, BB), 256>>>(embed, out);
    finalize_kernel<<<1, 256>>>(out, out_size);
}

// round 2
// speedup vs baseline: 1.2907x; 1.2907x over previous
#include <cuda_runtime.h>
#include <math.h>
#include <float.h>

#define BB   16
#define CC   512
#define TT   4096
#define EE   256
#define KK   1024
#define NN   (BB * TT)   // 65536

#define YS_STR 68
#define BS_STR 260
#define ES_STR 260

// Scratch (device globals -- no allocation allowed)
__device__ int          g_idx[NN];
__device__ float        g_e2[KK];
__device__ unsigned int g_hist[KK];
__device__ double       g_loss;

// ---------------------------------------------------------------------------
__global__ void init_kernel(const float* __restrict__ embed) {
    int k = blockIdx.x * blockDim.x + threadIdx.x;
    if (k < KK) {
        const float* row = embed + (size_t)k * EE;
        float s = 0.f;
#pragma unroll 8
        for (int e = 0; e < EE; e++) { float v = row[e]; s += v * v; }
        g_e2[k] = s;
        g_hist[k] = 0u;
    }
    if (k == 0) g_loss = 0.0;
}

// ---------------------------------------------------------------------------
// Fused: projection GEMM (64t x 256e x 512c) -> y in smem ->
//        distance GEMM (64n x 1024k x 256e) -> argmin -> loss/hist.
// Block: 256 threads (tx 0..31 -> e/k split-half, ty 0..7 -> n). 8x8 microtile.
// ---------------------------------------------------------------------------
__global__ __launch_bounds__(256, 2)
void fused_kernel(const float* __restrict__ x, const float* __restrict__ w,
                  const float* __restrict__ bias, const float* __restrict__ embed) {
    extern __shared__ float sm[];
    float* Ys = sm;                          // [256][YS_STR]  (e-major, n inner)
    float* As = sm + 256 * YS_STR;           // [16][64]       (c x t)
    float* Bs = As + 16 * 64;                // [16][BS_STR]   (c x e)
    float* Es = As;                          // union: [16][ES_STR] (e x k)

    __shared__ float sY2[64];
    __shared__ float lred[8];

    const int b   = blockIdx.x >> 6;
    const int t0  = (blockIdx.x & 63) * 64;
    const int tid = threadIdx.x;
    const int tx  = tid & 31;
    const int ty  = tid >> 5;

    // ---------------- Phase 1: projection ----------------
    float acc[8][8];
#pragma unroll
    for (int i = 0; i < 8; i++)
#pragma unroll
        for (int j = 0; j < 8; j++) acc[i][j] = 0.f;

    const int aC = tid >> 4;           // 0..15 (c)
    const int aT = (tid & 15) * 4;     // t offset
    const float* xbase = x + ((size_t)b * CC) * TT + t0;

    for (int c0 = 0; c0 < CC; c0 += 16) {
        float4 xv = *(const float4*)(xbase + (size_t)(c0 + aC) * TT + aT);
        *(float4*)&As[aC * 64 + aT] = xv;
        const float* wrow = w + (size_t)tid * CC + c0;   // e = tid
#pragma unroll
        for (int q = 0; q < 4; q++) {
            float4 wv = *(const float4*)(wrow + q * 4);
            Bs[(q * 4 + 0) * BS_STR + tid] = wv.x;
            Bs[(q * 4 + 1) * BS_STR + tid] = wv.y;
            Bs[(q * 4 + 2) * BS_STR + tid] = wv.z;
            Bs[(q * 4 + 3) * BS_STR + tid] = wv.w;
        }
        __syncthreads();
#pragma unroll
        for (int k2 = 0; k2 < 16; k2++) {
            float4 a0 = *(const float4*)&As[k2 * 64 + ty * 8];
            float4 a1 = *(const float4*)&As[k2 * 64 + ty * 8 + 4];
            float4 b0 = *(const float4*)&Bs[k2 * BS_STR + tx * 4];
            float4 b1 = *(const float4*)&Bs[k2 * BS_STR + 128 + tx * 4];
            float av[8] = {a0.x, a0.y, a0.z, a0.w, a1.x, a1.y, a1.z, a1.w};
            float bv[8] = {b0.x, b0.y, b0.z, b0.w, b1.x, b1.y, b1.z, b1.w};
#pragma unroll
            for (int i = 0; i < 8; i++)
#pragma unroll
                for (int j = 0; j < 8; j++) acc[i][j] += av[i] * bv[j];
        }
        __syncthreads();
    }

    // bias add, write Ys (e-major), per-n ||y||^2
    float4 bl = *(const float4*)(bias + tx * 4);
    float4 bh = *(const float4*)(bias + 128 + tx * 4);
    float bb[8] = {bl.x, bl.y, bl.z, bl.w, bh.x, bh.y, bh.z, bh.w};
#pragma unroll
    for (int i = 0; i < 8; i++) {
        float s = 0.f;
        int n = ty * 8 + i;
#pragma unroll
        for (int j = 0; j < 8; j++) {
            float yv = acc[i][j] + bb[j];
            int e = (j < 4) ? (tx * 4 + j) : (128 + tx * 4 + (j - 4));
            Ys[e * YS_STR + n] = yv;
            s += yv * yv;
        }
#pragma unroll
        for (int off = 16; off > 0; off >>= 1) s += __shfl_xor_sync(0xFFFFFFFFu, s, off);
        if (tx == 0) sY2[n] = s;
    }
    __syncthreads();

    // ---------------- Phase 2: distances + argmin ----------------
    float bestv[8];
    int   besti[8];
#pragma unroll
    for (int i = 0; i < 8; i++) { bestv[i] = FLT_MAX; besti[i] = 0; }

    for (int kc = 0; kc < 4; kc++) {
        float acc2[8][8];
#pragma unroll
        for (int i = 0; i < 8; i++)
#pragma unroll
            for (int j = 0; j < 8; j++) acc2[i][j] = 0.f;

        const float* ebase = embed + (size_t)(kc * 256) * EE;   // k = kc*256 + tid
        for (int e0 = 0; e0 < EE; e0 += 16) {
            const float* erow = ebase + (size_t)tid * EE + e0;
#pragma unroll
            for (int q = 0; q < 4; q++) {
                float4 ev = *(const float4*)(erow + q * 4);
                Es[(q * 4 + 0) * ES_STR + tid] = ev.x;
                Es[(q * 4 + 1) * ES_STR + tid] = ev.y;
                Es[(q * 4 + 2) * ES_STR + tid] = ev.z;
                Es[(q * 4 + 3) * ES_STR + tid] = ev.w;
            }
            __syncthreads();
#pragma unroll
            for (int k2 = 0; k2 < 16; k2++) {
                float4 a0 = *(const float4*)&Ys[(e0 + k2) * YS_STR + ty * 8];
                float4 a1 = *(const float4*)&Ys[(e0 + k2) * YS_STR + ty * 8 + 4];
                float4 b0 = *(const float4*)&Es[k2 * ES_STR + tx * 4];
                float4 b1 = *(const float4*)&Es[k2 * ES_STR + 128 + tx * 4];
                float av[8] = {a0.x, a0.y, a0.z, a0.w, a1.x, a1.y, a1.z, a1.w};
                float bv[8] = {b0.x, b0.y, b0.z, b0.w, b1.x, b1.y, b1.z, b1.w};
#pragma unroll
                for (int i = 0; i < 8; i++)
#pragma unroll
                    for (int j = 0; j < 8; j++) acc2[i][j] += av[i] * bv[j];
            }
            __syncthreads();
        }
        // fold into best (k ascending within thread: j=0..3 low half, 4..7 high)
#pragma unroll
        for (int j = 0; j < 8; j++) {
            int k = kc * 256 + ((j < 4) ? (tx * 4 + j) : (128 + tx * 4 + (j - 4)));
            float e2 = __ldg(&g_e2[k]);
#pragma unroll
            for (int i = 0; i < 8; i++) {
                float d = e2 - 2.0f * acc2[i][j];
                if (d < bestv[i] || (d == bestv[i] && k < besti[i])) { bestv[i] = d; besti[i] = k; }
            }
        }
    }

    // ---------------- Reduce across warp lanes (k coverage) ----------------
    float wloss = 0.f;
#pragma unroll
    for (int i = 0; i < 8; i++) {
        float v = bestv[i];
        int   ix = besti[i];
#pragma unroll
        for (int off = 16; off > 0; off >>= 1) {
            float ov = __shfl_xor_sync(0xFFFFFFFFu, v, off);
            int   oi = __shfl_xor_sync(0xFFFFFFFFu, ix, off);
            if (ov < v || (ov == v && oi < ix)) { v = ov; ix = oi; }
        }
        if (tx == 0) {
            int n = ty * 8 + i;
            g_idx[blockIdx.x * 64 + n] = ix;
            wloss += v + sY2[n];             // ||zq - y||^2 = (||e||^2 - 2 y.e) + ||y||^2
            atomicAdd(&g_hist[ix], 1u);
        }
    }
    if (tx == 0) lred[ty] = wloss;
    __syncthreads();
    if (tid == 0) {
        float s = 0.f;
#pragma unroll
        for (int wgi = 0; wgi < 8; wgi++) s += lred[wgi];
        atomicAdd(&g_loss, (double)s);
    }
}

// ---------------------------------------------------------------------------
// Gather + transpose output: out[b, e, t] = embed[idx[b*T+t], e]
// Coalesced embed reads (e contiguous per lane) and coalesced out writes
// (t contiguous per lane) via a padded 32x33 smem tile.
// ---------------------------------------------------------------------------
__global__ void out_kernel(const float* __restrict__ embed, float* __restrict__ out) {
    __shared__ float tile[32][33];
    __shared__ int sidx[32];
    const int t0 = blockIdx.x * 32;
    const int b  = blockIdx.y;
    const int tx = threadIdx.x & 31;
    const int ty = threadIdx.x >> 5;   // 0..7
    if (threadIdx.x < 32) sidx[threadIdx.x] = g_idx[b * TT + t0 + threadIdx.x];
    __syncthreads();
    for (int e0 = 0; e0 < EE; e0 += 32) {
#pragma unroll
        for (int q = 0; q < 4; q++) {
            int t = ty * 4 + q;
            tile[t][tx] = embed[(size_t)sidx[t] * EE + e0 + tx];
        }
        __syncthreads();
#pragma unroll
        for (int q = 0; q < 4; q++) {
            int e = e0 + ty * 4 + q;
            out[((size_t)(b * EE + e)) * TT + t0 + tx] = tile[tx][ty * 4 + q];
        }
        __syncthreads();
    }
}

// ---------------------------------------------------------------------------
__global__ void finalize_kernel(float* __restrict__ out, int out_size) {
    __shared__ float red[8];
    const int tid = threadIdx.x;  // 256
    float s = 0.f;
    for (int k = tid; k < KK; k += 256) {
        float p = (float)g_hist[k] / (float)NN;
        s += p * logf(p + 1e-10f);
    }
#pragma unroll
    for (int off = 16; off > 0; off >>= 1) s += __shfl_down_sync(0xFFFFFFFFu, s, off);
    if ((tid & 31) == 0) red[tid >> 5] = s;
    __syncthreads();
    if (tid == 0) {
        float tot = 0.f;
#pragma unroll
        for (int wgi = 0; wgi < 8; wgi++) tot += red[wgi];
        const float log_perp = -tot;
        const float loss = 0.25f * (float)(g_loss / ((double)NN * (double)EE));
        const float kld = logf((float)KK) * (float)TT;
        const long long base = (long long)NN * EE;
        if (base + 0 < out_size) out[base + 0] = loss;
        for (int i = 0; i < BB; i++)
            if (base + 1 + i < out_size) out[base + 1 + i] = kld;
        if (base + 1 + BB < out_size) out[base + 1 + BB] = log_perp;
    }
}

// ---------------------------------------------------------------------------
extern "C" void kernel_launch(void* const* d_in, const int* in_sizes, int n_in,
                              void* d_out, int out_size) {
    const float* x     = (const float*)d_in[0];
    const float* w     = (const float*)d_in[1];
    const float* bias  = (const float*)d_in[2];
    const float* embed = (const float*)d_in[3];
    float* out = (float*)d_out;

    static int smem_set = 0;
    const int smem_bytes = (256 * YS_STR + 16 * 64 + 16 * BS_STR) * 4;  // 90368
    if (!smem_set) {
        cudaFuncSetAttribute(fused_kernel, cudaFuncAttributeMaxDynamicSharedMemorySize, smem_bytes);
        smem_set = 1;
    }

    init_kernel<<<4, 256>>>(embed);
    fused_kernel<<<NN / 64, 256, smem_bytes>>>(x, w, bias, embed);
    out_kernel<<<dim3(TT / 32, BB), 256>>>(embed, out);
    finalize_kernel<<<1, 256>>>(out, out_size);
}

// round 5
// speedup vs baseline: 2.6818x; 2.0777x over previous
#include <cuda_runtime.h>
#include <cuda_bf16.h>
#include <math.h>
#include <float.h>
#include <stdint.h>

#define BB 16
#define CC 512
#define TT 4096
#define EE 256
#define KK 1024
#define NN (BB*TT)

// ---------------- dynamic smem layout (bytes) ----------------
// phase1: stage (fp32 x-transpose buffer) lives in the Y area (Y written later)
// phase1 mma: A (x^T tile) + B (w tile); phase2: A = Y chunks, B = embed tiles
#define OFF_Y_HI   0          // 4 chunks x [128][64] bf16 = 65536
#define OFF_Y_LO   65536      // 65536
#define OFF_A_HI   131072     // [128][64] bf16 = 16384   (phase1 only)
#define OFF_A_LO   147456     // 16384
#define OFF_B_HI   163840     // [256][64] bf16 = 32768
#define OFF_B_LO   196608     // 32768
#define SMEM_BYTES 229376
// reductions alias the A region (used only after phase-1 mma is done)
#define OFF_RED    131072     // y2s[128] f32
#define OFF_BVS    131584     // bvs[128][4] f32
#define OFF_BIS    133632     // bis[128][4] i32
#define OFF_LRED   135680     // lred[4] f32

#define STAGE_STR 132

#define SW128(o) ((o) ^ (((o) >> 3) & 0x70))

static __device__ __forceinline__ uint32_t smem_u32(const void* p) {
    uint32_t a;
    asm("{ .reg .u64 t; cvta.to.shared.u64 t, %1; cvt.u32.u64 %0, t; }" : "=r"(a) : "l"(p));
    return a;
}

static __device__ __forceinline__ void ldsm_x4(uint32_t* r, uint32_t addr) {
    asm volatile("ldmatrix.sync.aligned.m8n8.x4.shared.b16 {%0,%1,%2,%3}, [%4];"
                 : "=r"(r[0]), "=r"(r[1]), "=r"(r[2]), "=r"(r[3]) : "r"(addr));
}

static __device__ __forceinline__ void mma_bf16(float* c, const uint32_t* a,
                                                uint32_t b0, uint32_t b1) {
    asm volatile(
        "mma.sync.aligned.m16n8k16.row.col.f32.bf16.bf16.f32 "
        "{%0,%1,%2,%3}, {%4,%5,%6,%7}, {%8,%9}, {%0,%1,%2,%3};"
        : "+f"(c[0]), "+f"(c[1]), "+f"(c[2]), "+f"(c[3])
        : "r"(a[0]), "r"(a[1]), "r"(a[2]), "r"(a[3]), "r"(b0), "r"(b1));
}

static __device__ __forceinline__ void f2bf(float v, unsigned short& h, unsigned short& l) {
    __nv_bfloat16 hb = __float2bfloat16(v);
    h = __bfloat16_as_ushort(hb);
    l = __bfloat16_as_ushort(__float2bfloat16(v - __bfloat162float(hb)));
}

// ---------------- global scratch ----------------
__device__ int          g_idx[NN];
__device__ float        g_e2[KK];
__device__ unsigned int g_hist[KK];
__device__ double       g_loss;
__device__ uint4        g_wt4[2][8][2048];      // w tiles: [hi/lo][c-chunk][256e x 64c bf16, SW128]
__device__ uint4        g_et4[2][4][4][2048];   // embed:   [hi/lo][k-chunk][e-chunk][256k x 64e]

// ---------------------------------------------------------------------------
__global__ void init_kernel(const float* __restrict__ embed) {
    int k = blockIdx.x * blockDim.x + threadIdx.x;
    if (k < KK) {
        const float* row = embed + (size_t)k * EE;
        float s = 0.f;
#pragma unroll 8
        for (int e = 0; e < EE; e++) { float v = row[e]; s += v * v; }
        g_e2[k] = s;
        g_hist[k] = 0u;
    }
    if (k == 0) g_loss = 0.0;
}

// Convert w and embed into MMA-ready swizzled bf16 hi/lo tiles.
__global__ void prep_kernel(const float* __restrict__ w, const float* __restrict__ embed) {
    int i = blockIdx.x * 256 + threadIdx.x;      // 0 .. 262143
    {   // embed[k][e]
        int k = i >> 8, e = i & 255;
        float v = embed[i];
        unsigned short h, l; f2bf(v, h, l);
        int off = SW128((k & 255) * 128 + (e & 63) * 2);
        ((unsigned short*)g_et4[0][k >> 8][e >> 6])[off >> 1] = h;
        ((unsigned short*)g_et4[1][k >> 8][e >> 6])[off >> 1] = l;
    }
    if (i < 131072) {   // w[e][c]
        int e = i >> 9, c = i & 511;
        float v = w[i];
        unsigned short h, l; f2bf(v, h, l);
        int off = SW128(e * 128 + (c & 63) * 2);
        ((unsigned short*)g_wt4[0][c >> 6])[off >> 1] = h;
        ((unsigned short*)g_wt4[1][c >> 6])[off >> 1] = l;
    }
}

// ---------------------------------------------------------------------------
// Fused: proj (128t x 256e x 512c) -> Y bf16 hi/lo in smem ->
// distances (128n x 1024k x 256e) -> argmin/loss/hist. All GEMMs on
// mma.sync bf16 with 3-term hi/lo split into fp32 accumulators.
// 8 warps: m-split 2 (64 rows), n-split 4 (64 cols).
// ---------------------------------------------------------------------------
__global__ __launch_bounds__(256, 1)
void fused_kernel(const float* __restrict__ x, const float* __restrict__ bias) {
    extern __shared__ char sm[];
    const int tid  = threadIdx.x;
    const int wid  = tid >> 5;
    const int lane = tid & 31;
    const uint32_t smb = smem_u32(sm);

    const int b  = blockIdx.x >> 5;
    const int t0 = (blockIdx.x & 31) * 128;

    const int m0  = (wid & 1) * 64;
    const int n0w = (wid >> 1) * 64;
    const int g   = lane >> 2;       // fragment row-in-8
    const int qc  = lane & 3;        // fragment col quad
    const int rowL  = lane & 15;     // ldmatrix row
    const int chalf = (lane >> 4);   // ldmatrix 16B half

    float* y2s  = (float*)(sm + OFF_RED);
    float* bvs  = (float*)(sm + OFF_BVS);
    int*   bis  = (int*)  (sm + OFF_BIS);
    float* lred = (float*)(sm + OFF_LRED);

    float acc[4][8][4];
    float* stg = (float*)(sm + OFF_Y_HI);   // phase1 stage buffer (Y area)

    // ================= Phase 1: projection =================
#pragma unroll
    for (int mi = 0; mi < 4; mi++)
#pragma unroll
        for (int ni = 0; ni < 8; ni++)
#pragma unroll
            for (int q = 0; q < 4; q++) acc[mi][ni][q] = 0.f;

    for (int ci = 0; ci < 8; ci++) {
        const int c0 = ci * 64;
        __syncthreads();      // protect stage/B from previous iteration's readers
        // stage x chunk: 64 c x 128 t fp32, coalesced
#pragma unroll
        for (int p = 0; p < 8; p++) {
            int cl = p * 8 + wid;
            float4 v = *(const float4*)(x + ((size_t)(b * CC + c0 + cl)) * TT + t0 + lane * 4);
            *(float4*)(stg + cl * STAGE_STR + lane * 4) = v;
        }
        // copy w tiles (pre-swizzled bf16)
        {
            const uint4* sh = g_wt4[0][ci];
            const uint4* sl = g_wt4[1][ci];
#pragma unroll
            for (int q = 0; q < 8; q++) {
                int idx = q * 256 + tid;
                *(uint4*)(sm + OFF_B_HI + idx * 16) = sh[idx];
                *(uint4*)(sm + OFF_B_LO + idx * 16) = sl[idx];
            }
        }
        __syncthreads();
        // transpose + split x -> A tiles [t=128][c=64] bf16 hi/lo, swizzled
        {
            const int r = tid >> 1;
            const int half = tid & 1;
#pragma unroll
            for (int i2 = 0; i2 < 16; i2++) {
                float v0 = stg[(half * 32 + 2 * i2 + 0) * STAGE_STR + r];
                float v1 = stg[(half * 32 + 2 * i2 + 1) * STAGE_STR + r];
                unsigned short h0, l0, h1, l1;
                f2bf(v0, h0, l0); f2bf(v1, h1, l1);
                int off = SW128(r * 128 + half * 64 + i2 * 4);
                *(uint32_t*)(sm + OFF_A_HI + off) = (uint32_t)h0 | ((uint32_t)h1 << 16);
                *(uint32_t*)(sm + OFF_A_LO + off) = (uint32_t)l0 | ((uint32_t)l1 << 16);
            }
        }
        __syncthreads();
        // mma over this 64-wide c chunk
#pragma unroll
        for (int ks = 0; ks < 4; ks++) {
            uint32_t ah[4][4], al[4][4];
#pragma unroll
            for (int mi = 0; mi < 4; mi++) {
                int off = SW128((m0 + mi * 16 + rowL) * 128 + ks * 32 + chalf * 16);
                ldsm_x4(ah[mi], smb + OFF_A_HI + off);
                ldsm_x4(al[mi], smb + OFF_A_LO + off);
            }
#pragma unroll
            for (int np = 0; np < 4; np++) {
                uint32_t bh[4], bl[4];
                int off = SW128((n0w + np * 16 + rowL) * 128 + ks * 32 + chalf * 16);
                ldsm_x4(bh, smb + OFF_B_HI + off);
                ldsm_x4(bl, smb + OFF_B_LO + off);
#pragma unroll
                for (int mi = 0; mi < 4; mi++) {
                    float* cA = acc[mi][np * 2];
                    float* cB = acc[mi][np * 2 + 1];
                    mma_bf16(cA, ah[mi], bh[0], bh[2]);
                    mma_bf16(cB, ah[mi], bh[1], bh[3]);
                    mma_bf16(cA, ah[mi], bl[0], bl[2]);
                    mma_bf16(cB, ah[mi], bl[1], bl[3]);
                    mma_bf16(cA, al[mi], bh[0], bh[2]);
                    mma_bf16(cB, al[mi], bh[1], bh[3]);
                }
            }
        }
    }

    // ---------------- Phase 1 epilogue: bias, Y -> smem bf16 hi/lo, ||y||^2 ----------------
    __syncthreads();
    if (tid < 128) y2s[tid] = 0.f;
    __syncthreads();
#pragma unroll
    for (int mi = 0; mi < 4; mi++) {
#pragma unroll
        for (int rp = 0; rp < 2; rp++) {
            const int r = m0 + mi * 16 + g + rp * 8;
            float y2p = 0.f;
#pragma unroll
            for (int ni = 0; ni < 8; ni++) {
                const int e = n0w + ni * 8 + qc * 2;
                float v0 = acc[mi][ni][rp * 2 + 0] + __ldg(&bias[e]);
                float v1 = acc[mi][ni][rp * 2 + 1] + __ldg(&bias[e + 1]);
                y2p += v0 * v0 + v1 * v1;
                unsigned short h0, l0, h1, l1;
                f2bf(v0, h0, l0); f2bf(v1, h1, l1);
                const int off = SW128(r * 128 + (e & 63) * 2);
                const int cb = (e >> 6) * 16384;
                *(uint32_t*)(sm + OFF_Y_HI + cb + off) = (uint32_t)h0 | ((uint32_t)h1 << 16);
                *(uint32_t*)(sm + OFF_Y_LO + cb + off) = (uint32_t)l0 | ((uint32_t)l1 << 16);
            }
            y2p += __shfl_xor_sync(0xFFFFFFFFu, y2p, 1);
            y2p += __shfl_xor_sync(0xFFFFFFFFu, y2p, 2);
            if (qc == 0) atomicAdd(&y2s[r], y2p);
        }
    }

    // ================= Phase 2: distances + argmin =================
    float bestv[4][2];
    int   besti[4][2];
#pragma unroll
    for (int mi = 0; mi < 4; mi++) { bestv[mi][0] = bestv[mi][1] = FLT_MAX;
                                     besti[mi][0] = besti[mi][1] = 0; }

    for (int nt = 0; nt < 4; nt++) {
#pragma unroll
        for (int mi = 0; mi < 4; mi++)
#pragma unroll
            for (int ni = 0; ni < 8; ni++)
#pragma unroll
                for (int q = 0; q < 4; q++) acc[mi][ni][q] = 0.f;

        for (int ec = 0; ec < 4; ec++) {
            __syncthreads();
            const uint4* sh = g_et4[0][nt][ec];
            const uint4* sl = g_et4[1][nt][ec];
#pragma unroll
            for (int q = 0; q < 8; q++) {
                int idx = q * 256 + tid;
                *(uint4*)(sm + OFF_B_HI + idx * 16) = sh[idx];
                *(uint4*)(sm + OFF_B_LO + idx * 16) = sl[idx];
            }
            __syncthreads();
            const uint32_t yh = smb + OFF_Y_HI + ec * 16384;
            const uint32_t yl = smb + OFF_Y_LO + ec * 16384;
#pragma unroll
            for (int ks = 0; ks < 4; ks++) {
                uint32_t ah[4][4], al[4][4];
#pragma unroll
                for (int mi = 0; mi < 4; mi++) {
                    int off = SW128((m0 + mi * 16 + rowL) * 128 + ks * 32 + chalf * 16);
                    ldsm_x4(ah[mi], yh + off);
                    ldsm_x4(al[mi], yl + off);
                }
#pragma unroll
                for (int np = 0; np < 4; np++) {
                    uint32_t bh[4], bl[4];
                    int off = SW128((n0w + np * 16 + rowL) * 128 + ks * 32 + chalf * 16);
                    ldsm_x4(bh, smb + OFF_B_HI + off);
                    ldsm_x4(bl, smb + OFF_B_LO + off);
#pragma unroll
                    for (int mi = 0; mi < 4; mi++) {
                        float* cA = acc[mi][np * 2];
                        float* cB = acc[mi][np * 2 + 1];
                        mma_bf16(cA, ah[mi], bh[0], bh[2]);
                        mma_bf16(cB, ah[mi], bh[1], bh[3]);
                        mma_bf16(cA, ah[mi], bl[0], bl[2]);
                        mma_bf16(cB, ah[mi], bl[1], bl[3]);
                        mma_bf16(cA, al[mi], bh[0], bh[2]);
                        mma_bf16(cB, al[mi], bh[1], bh[3]);
                    }
                }
            }
        }
        // fold distances into per-row best (k ascending => strict < keeps lowest k)
#pragma unroll
        for (int ni = 0; ni < 8; ni++) {
            const int k0 = nt * 256 + n0w + ni * 8 + qc * 2;
            const float e2a = __ldg(&g_e2[k0]);
            const float e2b = __ldg(&g_e2[k0 + 1]);
#pragma unroll
            for (int mi = 0; mi < 4; mi++) {
#pragma unroll
                for (int rp = 0; rp < 2; rp++) {
                    float d0 = e2a - 2.0f * acc[mi][ni][rp * 2 + 0];
                    float d1 = e2b - 2.0f * acc[mi][ni][rp * 2 + 1];
                    if (d0 < bestv[mi][rp]) { bestv[mi][rp] = d0; besti[mi][rp] = k0; }
                    if (d1 < bestv[mi][rp]) { bestv[mi][rp] = d1; besti[mi][rp] = k0 + 1; }
                }
            }
        }
    }

    // ---------------- Final reduce: quad lanes, then 4 n-warps ----------------
#pragma unroll
    for (int mi = 0; mi < 4; mi++) {
#pragma unroll
        for (int rp = 0; rp < 2; rp++) {
            const int r = m0 + mi * 16 + g + rp * 8;
            float v = bestv[mi][rp];
            int   ix = besti[mi][rp];
#pragma unroll
            for (int d = 1; d <= 2; d <<= 1) {
                float ov = __shfl_xor_sync(0xFFFFFFFFu, v, d);
                int   oi = __shfl_xor_sync(0xFFFFFFFFu, ix, d);
                if (ov < v || (ov == v && oi < ix)) { v = ov; ix = oi; }
            }
            if (qc == 0) { bvs[r * 4 + (wid >> 1)] = v; bis[r * 4 + (wid >> 1)] = ix; }
        }
    }
    __syncthreads();
    if (tid < 128) {
        const int r = tid;
        float v = bvs[r * 4];
        int   ix = bis[r * 4];
#pragma unroll
        for (int j = 1; j < 4; j++) {
            float vj = bvs[r * 4 + j];
            int   ij = bis[r * 4 + j];
            if (vj < v || (vj == v && ij < ix)) { v = vj; ix = ij; }
        }
        g_idx[blockIdx.x * 128 + r] = ix;
        atomicAdd(&g_hist[ix], 1u);
        float lc = v + y2s[r];
#pragma unroll
        for (int off = 16; off > 0; off >>= 1) lc += __shfl_down_sync(0xFFFFFFFFu, lc, off);
        if (lane == 0) lred[wid] = lc;
    }
    __syncthreads();
    if (tid == 0)
        atomicAdd(&g_loss, (double)(lred[0] + lred[1] + lred[2] + lred[3]));
}

// ---------------------------------------------------------------------------
__global__ void out_kernel(const float* __restrict__ embed, float* __restrict__ out) {
    __shared__ float tile[32][33];
    __shared__ int sidx[32];
    const int t0 = blockIdx.x * 32;
    const int b  = blockIdx.y;
    const int tx = threadIdx.x & 31;
    const int ty = threadIdx.x >> 5;
    if (threadIdx.x < 32) sidx[threadIdx.x] = g_idx[b * TT + t0 + threadIdx.x];
    __syncthreads();
    for (int e0 = 0; e0 < EE; e0 += 32) {
#pragma unroll
        for (int q = 0; q < 4; q++) {
            int t = ty * 4 + q;
            tile[t][tx] = embed[(size_t)sidx[t] * EE + e0 + tx];
        }
        __syncthreads();
#pragma unroll
        for (int q = 0; q < 4; q++) {
            int e = e0 + ty * 4 + q;
            out[((size_t)(b * EE + e)) * TT + t0 + tx] = tile[tx][ty * 4 + q];
        }
        __syncthreads();
    }
}

// ---------------------------------------------------------------------------
__global__ void finalize_kernel(float* __restrict__ out, int out_size) {
    __shared__ float red[8];
    const int tid = threadIdx.x;
    float s = 0.f;
    for (int k = tid; k < KK; k += 256) {
        float p = (float)g_hist[k] / (float)NN;
        s += p * logf(p + 1e-10f);
    }
#pragma unroll
    for (int off = 16; off > 0; off >>= 1) s += __shfl_down_sync(0xFFFFFFFFu, s, off);
    if ((tid & 31) == 0) red[tid >> 5] = s;
    __syncthreads();
    if (tid == 0) {
        float tot = 0.f;
#pragma unroll
        for (int wgi = 0; wgi < 8; wgi++) tot += red[wgi];
        const float log_perp = -tot;
        const float loss = 0.25f * (float)(g_loss / ((double)NN * (double)EE));
        const float kld = logf((float)KK) * (float)TT;
        const long long base = (long long)NN * EE;
        if (base + 0 < out_size) out[base + 0] = loss;
        for (int i = 0; i < BB; i++)
            if (base + 1 + i < out_size) out[base + 1 + i] = kld;
        if (base + 1 + BB < out_size) out[base + 1 + BB] = log_perp;
    }
}

// ---------------------------------------------------------------------------
extern "C" void kernel_launch(void* const* d_in, const int* in_sizes, int n_in,
                              void* d_out, int out_size) {
    const float* x     = (const float*)d_in[0];
    const float* w     = (const float*)d_in[1];
    const float* bias  = (const float*)d_in[2];
    const float* embed = (const float*)d_in[3];
    float* out = (float*)d_out;

    static int attr_set = 0;
    if (!attr_set) {
        cudaFuncSetAttribute(fused_kernel, cudaFuncAttributeMaxDynamicSharedMemorySize, SMEM_BYTES);
        attr_set = 1;
    }

    init_kernel<<<4, 256>>>(embed);
    prep_kernel<<<1024, 256>>>(w, embed);
    fused_kernel<<<NN / 128, 256, SMEM_BYTES>>>(x, bias);
    out_kernel<<<dim3(TT / 32, BB), 256>>>(embed, out);
    finalize_kernel<<<1, 256>>>(out, out_size);
}

// round 7
// speedup vs baseline: 3.0573x; 1.1400x over previous
#include <cuda_runtime.h>
#include <cuda_bf16.h>
#include <math.h>
#include <float.h>
#include <stdint.h>

#define BB 16
#define CC 512
#define TT 4096
#define EE 256
#define KK 1024
#define NN (BB*TT)

// ---------------- dynamic smem layout (bytes) ----------------
// Phase 1: stage (x fp32) | A hi/lo | w double-buffers
#define OFF_STAGE  0                   // 64 x 132 fp32 = 33792
#define OFF_A_HI   34816               // 16384
#define OFF_A_LO   51200               // 16384
#define OFF_WBUF   67584               // 2 x (32768 hi + 32768 lo) = 131072 -> 198656
// Phase 2: Y hi/lo | embed double-buffers | reductions
#define OFF_Y_HI   0                   // 4 x 16384 = 65536
#define OFF_Y_LO   65536               // 65536
#define OFF_EBUF   131072              // 2 x (16384 hi + 16384 lo) = 65536 -> 196608
#define OFF_RED    196608              // y2s[128] f32
#define OFF_BVS    197120              // [128][4] f32
#define OFF_BIS    199168              // [128][4] i32
#define OFF_LRED   201216              // [8] f32
#define SMEM_BYTES 229376

#define STAGE_STR 132

#define SW128(o) ((o) ^ (((o) >> 3) & 0x70))

static __device__ __forceinline__ uint32_t smem_u32(const void* p) {
    uint32_t a;
    asm("{ .reg .u64 t; cvta.to.shared.u64 t, %1; cvt.u32.u64 %0, t; }" : "=r"(a) : "l"(p));
    return a;
}

static __device__ __forceinline__ void cp16(uint32_t dst, const void* src) {
    asm volatile("cp.async.cg.shared.global [%0], [%1], 16;"
                 :: "r"(dst), "l"(__cvta_generic_to_global(src)));
}
#define CP_COMMIT() asm volatile("cp.async.commit_group;" ::: "memory")
#define CP_WAIT0()  asm volatile("cp.async.wait_group 0;" ::: "memory")

static __device__ __forceinline__ void ldsm_x4(uint32_t* r, uint32_t addr) {
    asm volatile("ldmatrix.sync.aligned.m8n8.x4.shared.b16 {%0,%1,%2,%3}, [%4];"
                 : "=r"(r[0]), "=r"(r[1]), "=r"(r[2]), "=r"(r[3]) : "r"(addr));
}

static __device__ __forceinline__ void mma_bf16(float* c, const uint32_t* a,
                                                uint32_t b0, uint32_t b1) {
    asm volatile(
        "mma.sync.aligned.m16n8k16.row.col.f32.bf16.bf16.f32 "
        "{%0,%1,%2,%3}, {%4,%5,%6,%7}, {%8,%9}, {%0,%1,%2,%3};"
        : "+f"(c[0]), "+f"(c[1]), "+f"(c[2]), "+f"(c[3])
        : "r"(a[0]), "r"(a[1]), "r"(a[2]), "r"(a[3]), "r"(b0), "r"(b1));
}

static __device__ __forceinline__ void f2bf(float v, unsigned short& h, unsigned short& l) {
    __nv_bfloat16 hb = __float2bfloat16(v);
    h = __bfloat16_as_ushort(hb);
    l = __bfloat16_as_ushort(__float2bfloat16(v - __bfloat162float(hb)));
}

// ---------------- global scratch ----------------
__device__ int          g_idx[NN];
__device__ float        g_e2[KK];
__device__ unsigned int g_hist[KK];
__device__ double       g_loss;
__device__ uint4        g_wt4[2][8][2048];      // w:     [hi/lo][c-chunk][256e x 64c bf16, SW128]
__device__ uint4        g_et4[2][8][4][1024];   // embed: [hi/lo][k-chunk(128)][e-chunk][128k x 64e]

// ---------------------------------------------------------------------------
__global__ void init_kernel(const float* __restrict__ embed) {
    int k = blockIdx.x * blockDim.x + threadIdx.x;
    if (k < KK) {
        const float* row = embed + (size_t)k * EE;
        float s = 0.f;
#pragma unroll 8
        for (int e = 0; e < EE; e++) { float v = row[e]; s += v * v; }
        g_e2[k] = s;
        g_hist[k] = 0u;
    }
    if (k == 0) g_loss = 0.0;
}

// Convert w and embed into MMA-ready swizzled bf16 hi/lo tiles.
__global__ void prep_kernel(const float* __restrict__ w, const float* __restrict__ embed) {
    int i = blockIdx.x * 256 + threadIdx.x;      // 0 .. 262143
    {   // embed[k][e] -> [kt(8)][ec(4)] tiles of 128k x 64e
        int k = i >> 8, e = i & 255;
        float v = embed[i];
        unsigned short h, l; f2bf(v, h, l);
        int off = SW128((k & 127) * 128 + (e & 63) * 2);
        ((unsigned short*)g_et4[0][k >> 7][e >> 6])[off >> 1] = h;
        ((unsigned short*)g_et4[1][k >> 7][e >> 6])[off >> 1] = l;
    }
    if (i < 131072) {   // w[e][c] -> [ci(8)] tiles of 256e x 64c
        int e = i >> 9, c = i & 511;
        float v = w[i];
        unsigned short h, l; f2bf(v, h, l);
        int off = SW128(e * 128 + (c & 63) * 2);
        ((unsigned short*)g_wt4[0][c >> 6])[off >> 1] = h;
        ((unsigned short*)g_wt4[1][c >> 6])[off >> 1] = l;
    }
}

// ---------------------------------------------------------------------------
// Fused: proj (128t x 256e x 512c) -> Y bf16 hi/lo in smem ->
// distances (128n x 1024k x 256e) -> argmin/loss/hist.
// 3-term bf16-split mma.sync, cp.async double-buffered operand streams.
// ---------------------------------------------------------------------------
__global__ __launch_bounds__(256, 1)
void fused_kernel(const float* __restrict__ x, const float* __restrict__ bias) {
    extern __shared__ char sm[];
    const int tid  = threadIdx.x;
    const int wid  = tid >> 5;
    const int lane = tid & 31;
    const uint32_t smb = smem_u32(sm);

    const int b  = blockIdx.x >> 5;
    const int t0 = (blockIdx.x & 31) * 128;

    const int m0   = (wid & 1) * 64;
    const int n0w  = (wid >> 1) * 64;    // phase1: 64-col slice of 256
    const int n0w2 = (wid >> 1) * 32;    // phase2: 32-col slice of 128
    const int g    = lane >> 2;
    const int qc   = lane & 3;
    const int rowL  = lane & 15;
    const int chalf = (lane >> 4);

    float* y2s  = (float*)(sm + OFF_RED);
    float* bvs  = (float*)(sm + OFF_BVS);
    int*   bis  = (int*)  (sm + OFF_BIS);
    float* lred = (float*)(sm + OFF_LRED);
    float* stg  = (float*)(sm + OFF_STAGE);

    float acc[4][8][4];

    // -------- prefetch helpers (lambdas) --------
    auto prefetch_x = [&](int ci) {
        const int c0 = ci * 64;
#pragma unroll
        for (int p = 0; p < 8; p++) {
            int cl = p * 8 + wid;
            cp16(smb + OFF_STAGE + (cl * STAGE_STR + lane * 4) * 4,
                 x + ((size_t)(b * CC + c0 + cl)) * TT + t0 + lane * 4);
        }
    };
    auto prefetch_w = [&](int ci) {
        const uint32_t base = smb + OFF_WBUF + (ci & 1) * 65536;
#pragma unroll
        for (int q = 0; q < 8; q++) {
            int idx = q * 256 + tid;
            cp16(base + idx * 16, &g_wt4[0][ci][idx]);
            cp16(base + 32768 + idx * 16, &g_wt4[1][ci][idx]);
        }
    };
    auto prefetch_e = [&](int it) {
        const int kt = it >> 2, ec = it & 3;
        const uint32_t base = smb + OFF_EBUF + (it & 1) * 32768;
#pragma unroll
        for (int q = 0; q < 4; q++) {
            int idx = q * 256 + tid;
            cp16(base + idx * 16, &g_et4[0][kt][ec][idx]);
            cp16(base + 16384 + idx * 16, &g_et4[1][kt][ec][idx]);
        }
    };

    // ================= Phase 1: projection =================
#pragma unroll
    for (int mi = 0; mi < 4; mi++)
#pragma unroll
        for (int ni = 0; ni < 8; ni++)
#pragma unroll
            for (int q = 0; q < 4; q++) acc[mi][ni][q] = 0.f;

    prefetch_x(0); prefetch_w(0); CP_COMMIT();

    for (int ci = 0; ci < 8; ci++) {
        CP_WAIT0();
        __syncthreads();                 // chunk ci data visible; mma(ci-1) done by all
        // transpose + split x -> A tiles [t=128][c=64] bf16 hi/lo, swizzled
        {
            const int r = tid >> 1;
            const int half = tid & 1;
#pragma unroll
            for (int i2 = 0; i2 < 16; i2++) {
                float v0 = stg[(half * 32 + 2 * i2 + 0) * STAGE_STR + r];
                float v1 = stg[(half * 32 + 2 * i2 + 1) * STAGE_STR + r];
                unsigned short h0, l0, h1, l1;
                f2bf(v0, h0, l0); f2bf(v1, h1, l1);
                int off = SW128(r * 128 + half * 64 + i2 * 4);
                *(uint32_t*)(sm + OFF_A_HI + off) = (uint32_t)h0 | ((uint32_t)h1 << 16);
                *(uint32_t*)(sm + OFF_A_LO + off) = (uint32_t)l0 | ((uint32_t)l1 << 16);
            }
        }
        __syncthreads();                 // stage free; A ready
        if (ci + 1 < 8) { prefetch_x(ci + 1); prefetch_w(ci + 1); }
        CP_COMMIT();

        const uint32_t wb = smb + OFF_WBUF + (ci & 1) * 65536;
#pragma unroll
        for (int ks = 0; ks < 4; ks++) {
            uint32_t ah[4][4], al[4][4];
#pragma unroll
            for (int mi = 0; mi < 4; mi++) {
                int off = SW128((m0 + mi * 16 + rowL) * 128 + ks * 32 + chalf * 16);
                ldsm_x4(ah[mi], smb + OFF_A_HI + off);
                ldsm_x4(al[mi], smb + OFF_A_LO + off);
            }
#pragma unroll
            for (int np = 0; np < 4; np++) {
                uint32_t bh[4], bl[4];
                int off = SW128((n0w + np * 16 + rowL) * 128 + ks * 32 + chalf * 16);
                ldsm_x4(bh, wb + off);
                ldsm_x4(bl, wb + 32768 + off);
#pragma unroll
                for (int mi = 0; mi < 4; mi++) {
                    float* cA = acc[mi][np * 2];
                    float* cB = acc[mi][np * 2 + 1];
                    mma_bf16(cA, ah[mi], bh[0], bh[2]);
                    mma_bf16(cB, ah[mi], bh[1], bh[3]);
                    mma_bf16(cA, ah[mi], bl[0], bl[2]);
                    mma_bf16(cB, ah[mi], bl[1], bl[3]);
                    mma_bf16(cA, al[mi], bh[0], bh[2]);
                    mma_bf16(cB, al[mi], bh[1], bh[3]);
                }
            }
        }
    }

    // ---------------- Phase 1 epilogue: bias, Y -> smem bf16 hi/lo, ||y||^2 ----------------
    __syncthreads();                     // all mma done; stage/A/wbuf dead
    if (tid < 128) y2s[tid] = 0.f;
    __syncthreads();
#pragma unroll
    for (int mi = 0; mi < 4; mi++) {
#pragma unroll
        for (int rp = 0; rp < 2; rp++) {
            const int r = m0 + mi * 16 + g + rp * 8;
            float y2p = 0.f;
#pragma unroll
            for (int ni = 0; ni < 8; ni++) {
                const int e = n0w + ni * 8 + qc * 2;
                float v0 = acc[mi][ni][rp * 2 + 0] + __ldg(&bias[e]);
                float v1 = acc[mi][ni][rp * 2 + 1] + __ldg(&bias[e + 1]);
                y2p += v0 * v0 + v1 * v1;
                unsigned short h0, l0, h1, l1;
                f2bf(v0, h0, l0); f2bf(v1, h1, l1);
                const int off = SW128(r * 128 + (e & 63) * 2);
                const int cb = (e >> 6) * 16384;
                *(uint32_t*)(sm + OFF_Y_HI + cb + off) = (uint32_t)h0 | ((uint32_t)h1 << 16);
                *(uint32_t*)(sm + OFF_Y_LO + cb + off) = (uint32_t)l0 | ((uint32_t)l1 << 16);
            }
            y2p += __shfl_xor_sync(0xFFFFFFFFu, y2p, 1);
            y2p += __shfl_xor_sync(0xFFFFFFFFu, y2p, 2);
            if (qc == 0) atomicAdd(&y2s[r], y2p);
        }
    }

    // ================= Phase 2: distances + argmin =================
    float bestv[4][2];
    int   besti[4][2];
#pragma unroll
    for (int mi = 0; mi < 4; mi++) { bestv[mi][0] = bestv[mi][1] = FLT_MAX;
                                     besti[mi][0] = besti[mi][1] = 0; }

    prefetch_e(0); CP_COMMIT();

    for (int it = 0; it < 32; it++) {
        const int kt = it >> 2, ec = it & 3;
        CP_WAIT0();
        __syncthreads();                 // chunk it ready; mma(it-1) done by all (Y ready at it=0)
        if (it + 1 < 32) prefetch_e(it + 1);
        CP_COMMIT();

        if (ec == 0) {
#pragma unroll
            for (int mi = 0; mi < 4; mi++)
#pragma unroll
                for (int ni = 0; ni < 4; ni++)
#pragma unroll
                    for (int q = 0; q < 4; q++) acc[mi][ni][q] = 0.f;
        }

        const uint32_t eb = smb + OFF_EBUF + (it & 1) * 32768;
        const uint32_t yh = smb + OFF_Y_HI + ec * 16384;
        const uint32_t yl = smb + OFF_Y_LO + ec * 16384;
#pragma unroll
        for (int ks = 0; ks < 4; ks++) {
            uint32_t ah[4][4], al[4][4];
#pragma unroll
            for (int mi = 0; mi < 4; mi++) {
                int off = SW128((m0 + mi * 16 + rowL) * 128 + ks * 32 + chalf * 16);
                ldsm_x4(ah[mi], yh + off);
                ldsm_x4(al[mi], yl + off);
            }
#pragma unroll
            for (int np = 0; np < 2; np++) {
                uint32_t bh[4], bl[4];
                int off = SW128((n0w2 + np * 16 + rowL) * 128 + ks * 32 + chalf * 16);
                ldsm_x4(bh, eb + off);
                ldsm_x4(bl, eb + 16384 + off);
#pragma unroll
                for (int mi = 0; mi < 4; mi++) {
                    float* cA = acc[mi][np * 2];
                    float* cB = acc[mi][np * 2 + 1];
                    mma_bf16(cA, ah[mi], bh[0], bh[2]);
                    mma_bf16(cB, ah[mi], bh[1], bh[3]);
                    mma_bf16(cA, ah[mi], bl[0], bl[2]);
                    mma_bf16(cB, ah[mi], bl[1], bl[3]);
                    mma_bf16(cA, al[mi], bh[0], bh[2]);
                    mma_bf16(cB, al[mi], bh[1], bh[3]);
                }
            }
        }

        if (ec == 3) {
            // fold distances: k ascending within thread -> strict < keeps lowest k
#pragma unroll
            for (int ni = 0; ni < 4; ni++) {
                const int k0 = kt * 128 + n0w2 + (ni >> 1) * 16 + (ni & 1) * 8 + qc * 2;
                const float e2a = __ldg(&g_e2[k0]);
                const float e2b = __ldg(&g_e2[k0 + 1]);
#pragma unroll
                for (int mi = 0; mi < 4; mi++) {
#pragma unroll
                    for (int rp = 0; rp < 2; rp++) {
                        float d0 = e2a - 2.0f * acc[mi][ni][rp * 2 + 0];
                        float d1 = e2b - 2.0f * acc[mi][ni][rp * 2 + 1];
                        if (d0 < bestv[mi][rp]) { bestv[mi][rp] = d0; besti[mi][rp] = k0; }
                        if (d1 < bestv[mi][rp]) { bestv[mi][rp] = d1; besti[mi][rp] = k0 + 1; }
                    }
                }
            }
        }
    }

    // ---------------- Final reduce: quad lanes, then 4 n-warp groups ----------------
#pragma unroll
    for (int mi = 0; mi < 4; mi++) {
#pragma unroll
        for (int rp = 0; rp < 2; rp++) {
            const int r = m0 + mi * 16 + g + rp * 8;
            float v = bestv[mi][rp];
            int   ix = besti[mi][rp];
#pragma unroll
            for (int d = 1; d <= 2; d <<= 1) {
                float ov = __shfl_xor_sync(0xFFFFFFFFu, v, d);
                int   oi = __shfl_xor_sync(0xFFFFFFFFu, ix, d);
                if (ov < v || (ov == v && oi < ix)) { v = ov; ix = oi; }
            }
            if (qc == 0) { bvs[r * 4 + (wid >> 1)] = v; bis[r * 4 + (wid >> 1)] = ix; }
        }
    }
    __syncthreads();
    if (tid < 128) {
        const int r = tid;
        float v = bvs[r * 4];
        int   ix = bis[r * 4];
#pragma unroll
        for (int j = 1; j < 4; j++) {
            float vj = bvs[r * 4 + j];
            int   ij = bis[r * 4 + j];
            if (vj < v || (vj == v && ij < ix)) { v = vj; ix = ij; }
        }
        g_idx[blockIdx.x * 128 + r] = ix;
        atomicAdd(&g_hist[ix], 1u);
        float lc = v + y2s[r];
#pragma unroll
        for (int off = 16; off > 0; off >>= 1) lc += __shfl_down_sync(0xFFFFFFFFu, lc, off);
        if (lane == 0) lred[wid] = lc;
    }
    __syncthreads();
    if (tid == 0)
        atomicAdd(&g_loss, (double)(lred[0] + lred[1] + lred[2] + lred[3]));
}

// ---------------------------------------------------------------------------
__global__ void out_kernel(const float* __restrict__ embed, float* __restrict__ out) {
    __shared__ float tile[32][33];
    __shared__ int sidx[32];
    const int t0 = blockIdx.x * 32;
    const int b  = blockIdx.y;
    const int tx = threadIdx.x & 31;
    const int ty = threadIdx.x >> 5;
    if (threadIdx.x < 32) sidx[threadIdx.x] = g_idx[b * TT + t0 + threadIdx.x];
    __syncthreads();
    for (int e0 = 0; e0 < EE; e0 += 32) {
#pragma unroll
        for (int q = 0; q < 4; q++) {
            int t = ty * 4 + q;
            tile[t][tx] = embed[(size_t)sidx[t] * EE + e0 + tx];
        }
        __syncthreads();
#pragma unroll
        for (int q = 0; q < 4; q++) {
            int e = e0 + ty * 4 + q;
            out[((size_t)(b * EE + e)) * TT + t0 + tx] = tile[tx][ty * 4 + q];
        }
        __syncthreads();
    }
}

// ---------------------------------------------------------------------------
__global__ void finalize_kernel(float* __restrict__ out, int out_size) {
    __shared__ float red[8];
    const int tid = threadIdx.x;
    float s = 0.f;
    for (int k = tid; k < KK; k += 256) {
        float p = (float)g_hist[k] / (float)NN;
        s += p * logf(p + 1e-10f);
    }
#pragma unroll
    for (int off = 16; off > 0; off >>= 1) s += __shfl_down_sync(0xFFFFFFFFu, s, off);
    if ((tid & 31) == 0) red[tid >> 5] = s;
    __syncthreads();
    if (tid == 0) {
        float tot = 0.f;
#pragma unroll
        for (int wgi = 0; wgi < 8; wgi++) tot += red[wgi];
        const float log_perp = -tot;
        const float loss = 0.25f * (float)(g_loss / ((double)NN * (double)EE));
        const float kld = logf((float)KK) * (float)TT;
        const long long base = (long long)NN * EE;
        if (base + 0 < out_size) out[base + 0] = loss;
        for (int i = 0; i < BB; i++)
            if (base + 1 + i < out_size) out[base + 1 + i] = kld;
        if (base + 1 + BB < out_size) out[base + 1 + BB] = log_perp;
    }
}

// ---------------------------------------------------------------------------
extern "C" void kernel_launch(void* const* d_in, const int* in_sizes, int n_in,
                              void* d_out, int out_size) {
    const float* x     = (const float*)d_in[0];
    const float* w     = (const float*)d_in[1];
    const float* bias  = (const float*)d_in[2];
    const float* embed = (const float*)d_in[3];
    float* out = (float*)d_out;

    static int attr_set = 0;
    if (!attr_set) {
        cudaFuncSetAttribute(fused_kernel, cudaFuncAttributeMaxDynamicSharedMemorySize, SMEM_BYTES);
        attr_set = 1;
    }

    init_kernel<<<4, 256>>>(embed);
    prep_kernel<<<1024, 256>>>(w, embed);
    fused_kernel<<<NN / 128, 256, SMEM_BYTES>>>(x, bias);
    out_kernel<<<dim3(TT / 32, BB), 256>>>(embed, out);
    finalize_kernel<<<1, 256>>>(out, out_size);
}

// round 9
// speedup vs baseline: 3.5138x; 1.1493x over previous
#include <cuda_runtime.h>
#include <cuda_bf16.h>
#include <math.h>
#include <float.h>
#include <stdint.h>

#define BB 16
#define CC 512
#define TT 4096
#define EE 256
#define KK 1024
#define NN (BB*TT)

// ---------------- dynamic smem layout (bytes) ----------------
// Phase 1: stage (x fp32) | A hi/lo | w double-buffers
#define OFF_STAGE  0                   // 64 x 132 fp32 = 33792
#define OFF_A_HI   34816               // 16384
#define OFF_A_LO   51200               // 16384
#define OFF_WBUF   67584               // 2 x (32768 hi + 32768 lo) = 131072 -> 198656
// Phase 2: Y hi/lo | embed hi double-buffers | candidates | reductions
#define OFF_Y_HI   0                   // 4 x 16384 = 65536
#define OFF_Y_LO   65536               // 65536
#define OFF_EBUF   131072              // 2 x 32768 (hi only) = 65536 -> 196608
#define OFF_CV     131072              // cand values  [128][32] f32 = 16384 (after mma loop)
#define OFF_CI     147456              // cand indices [128][32] i32 = 16384
#define OFF_RED    196608              // y2s[128] f32
#define OFF_LRED   197120              // [8] f32
#define SMEM_BYTES 229376

#define STAGE_STR 132
#define MARGIN 4.0f

#define SW128(o) ((o) ^ (((o) >> 3) & 0x70))

static __device__ __forceinline__ uint32_t smem_u32(const void* p) {
    uint32_t a;
    asm("{ .reg .u64 t; cvta.to.shared.u64 t, %1; cvt.u32.u64 %0, t; }" : "=r"(a) : "l"(p));
    return a;
}

static __device__ __forceinline__ void cp16(uint32_t dst, const void* src) {
    asm volatile("cp.async.cg.shared.global [%0], [%1], 16;"
                 :: "r"(dst), "l"(__cvta_generic_to_global(src)));
}
#define CP_COMMIT() asm volatile("cp.async.commit_group;" ::: "memory")
#define CP_WAIT0()  asm volatile("cp.async.wait_group 0;" ::: "memory")

static __device__ __forceinline__ void ldsm_x4(uint32_t* r, uint32_t addr) {
    asm volatile("ldmatrix.sync.aligned.m8n8.x4.shared.b16 {%0,%1,%2,%3}, [%4];"
                 : "=r"(r[0]), "=r"(r[1]), "=r"(r[2]), "=r"(r[3]) : "r"(addr));
}

static __device__ __forceinline__ void mma_bf16(float* c, const uint32_t* a,
                                                uint32_t b0, uint32_t b1) {
    asm volatile(
        "mma.sync.aligned.m16n8k16.row.col.f32.bf16.bf16.f32 "
        "{%0,%1,%2,%3}, {%4,%5,%6,%7}, {%8,%9}, {%0,%1,%2,%3};"
        : "+f"(c[0]), "+f"(c[1]), "+f"(c[2]), "+f"(c[3])
        : "r"(a[0]), "r"(a[1]), "r"(a[2]), "r"(a[3]), "r"(b0), "r"(b1));
}

static __device__ __forceinline__ void f2bf(float v, unsigned short& h, unsigned short& l) {
    __nv_bfloat16 hb = __float2bfloat16(v);
    h = __bfloat16_as_ushort(hb);
    l = __bfloat16_as_ushort(__float2bfloat16(v - __bfloat162float(hb)));
}

static __device__ __forceinline__ float bf_hi(uint32_t w) {
    return __bfloat162float(__ushort_as_bfloat16((unsigned short)(w >> 16)));
}
static __device__ __forceinline__ float bf_lo(uint32_t w) {
    return __bfloat162float(__ushort_as_bfloat16((unsigned short)(w & 0xFFFF)));
}

// ---------------- global scratch ----------------
__device__ int          g_idx[NN];
__device__ float        g_e2[KK];
__device__ unsigned int g_hist[KK];
__device__ double       g_loss;
__device__ uint4        g_wt4[2][8][2048];      // w:     [hi/lo][c-chunk][256e x 64c bf16, SW128]
__device__ uint4        g_et4[4][4][2048];      // embed hi: [k-chunk(256)][e-chunk][256k x 64e]

// ---------------------------------------------------------------------------
__global__ void init_kernel(const float* __restrict__ embed) {
    int k = blockIdx.x * blockDim.x + threadIdx.x;
    if (k < KK) {
        const float* row = embed + (size_t)k * EE;
        float s = 0.f;
#pragma unroll 8
        for (int e = 0; e < EE; e++) { float v = row[e]; s += v * v; }
        g_e2[k] = s;
        g_hist[k] = 0u;
    }
    if (k == 0) g_loss = 0.0;
}

// Convert w (hi/lo) and embed (hi only) into MMA-ready swizzled bf16 tiles.
__global__ void prep_kernel(const float* __restrict__ w, const float* __restrict__ embed) {
    int i = blockIdx.x * 256 + threadIdx.x;      // 0 .. 262143
    {   // embed[k][e] -> [kt(4)][ec(4)] tiles of 256k x 64e (hi only)
        int k = i >> 8, e = i & 255;
        float v = embed[i];
        unsigned short h = __bfloat16_as_ushort(__float2bfloat16(v));
        int off = SW128((k & 255) * 128 + (e & 63) * 2);
        ((unsigned short*)g_et4[k >> 8][e >> 6])[off >> 1] = h;
    }
    if (i < 131072) {   // w[e][c] -> [ci(8)] tiles of 256e x 64c
        int e = i >> 9, c = i & 511;
        float v = w[i];
        unsigned short h, l; f2bf(v, h, l);
        int off = SW128(e * 128 + (c & 63) * 2);
        ((unsigned short*)g_wt4[0][c >> 6])[off >> 1] = h;
        ((unsigned short*)g_wt4[1][c >> 6])[off >> 1] = l;
    }
}

// ---------------------------------------------------------------------------
// Fused: proj (3-term split, exact) -> Y bf16 hi/lo in smem ->
// screened distances (hi*hi only) -> top-2 candidates -> exact fp32 re-check
// -> argmin/loss/hist.
// ---------------------------------------------------------------------------
__global__ __launch_bounds__(256, 1)
void fused_kernel(const float* __restrict__ x, const float* __restrict__ bias,
                  const float* __restrict__ embed) {
    extern __shared__ char sm[];
    const int tid  = threadIdx.x;
    const int wid  = tid >> 5;
    const int lane = tid & 31;
    const uint32_t smb = smem_u32(sm);

    const int b  = blockIdx.x >> 5;
    const int t0 = (blockIdx.x & 31) * 128;
    const int n0 = blockIdx.x * 128;

    const int m0   = (wid & 1) * 64;
    const int n0w  = (wid >> 1) * 64;
    const int g    = lane >> 2;
    const int qc   = lane & 3;
    const int rowL  = lane & 15;
    const int chalf = (lane >> 4);

    float* y2s  = (float*)(sm + OFF_RED);
    float* lred = (float*)(sm + OFF_LRED);
    float* stg  = (float*)(sm + OFF_STAGE);

    float acc[4][8][4];

    auto prefetch_x = [&](int ci) {
        const int c0 = ci * 64;
#pragma unroll
        for (int p = 0; p < 8; p++) {
            int cl = p * 8 + wid;
            cp16(smb + OFF_STAGE + (cl * STAGE_STR + lane * 4) * 4,
                 x + ((size_t)(b * CC + c0 + cl)) * TT + t0 + lane * 4);
        }
    };
    auto prefetch_w = [&](int ci) {
        const uint32_t base = smb + OFF_WBUF + (ci & 1) * 65536;
#pragma unroll
        for (int q = 0; q < 8; q++) {
            int idx = q * 256 + tid;
            cp16(base + idx * 16, &g_wt4[0][ci][idx]);
            cp16(base + 32768 + idx * 16, &g_wt4[1][ci][idx]);
        }
    };
    auto prefetch_e = [&](int it) {
        const int kt = it >> 2, ec = it & 3;
        const uint32_t base = smb + OFF_EBUF + (it & 1) * 32768;
#pragma unroll
        for (int q = 0; q < 8; q++) {
            int idx = q * 256 + tid;
            cp16(base + idx * 16, &g_et4[kt][ec][idx]);
        }
    };

    // ================= Phase 1: projection (3-term split) =================
#pragma unroll
    for (int mi = 0; mi < 4; mi++)
#pragma unroll
        for (int ni = 0; ni < 8; ni++)
#pragma unroll
            for (int q = 0; q < 4; q++) acc[mi][ni][q] = 0.f;

    prefetch_x(0); prefetch_w(0); CP_COMMIT();

    for (int ci = 0; ci < 8; ci++) {
        CP_WAIT0();
        __syncthreads();
        {
            const int r = tid >> 1;
            const int half = tid & 1;
#pragma unroll
            for (int i2 = 0; i2 < 16; i2++) {
                float v0 = stg[(half * 32 + 2 * i2 + 0) * STAGE_STR + r];
                float v1 = stg[(half * 32 + 2 * i2 + 1) * STAGE_STR + r];
                unsigned short h0, l0, h1, l1;
                f2bf(v0, h0, l0); f2bf(v1, h1, l1);
                int off = SW128(r * 128 + half * 64 + i2 * 4);
                *(uint32_t*)(sm + OFF_A_HI + off) = (uint32_t)h0 | ((uint32_t)h1 << 16);
                *(uint32_t*)(sm + OFF_A_LO + off) = (uint32_t)l0 | ((uint32_t)l1 << 16);
            }
        }
        __syncthreads();
        if (ci + 1 < 8) { prefetch_x(ci + 1); prefetch_w(ci + 1); }
        CP_COMMIT();

        const uint32_t wb = smb + OFF_WBUF + (ci & 1) * 65536;
#pragma unroll
        for (int ks = 0; ks < 4; ks++) {
            uint32_t ah[4][4], al[4][4];
#pragma unroll
            for (int mi = 0; mi < 4; mi++) {
                int off = SW128((m0 + mi * 16 + rowL) * 128 + ks * 32 + chalf * 16);
                ldsm_x4(ah[mi], smb + OFF_A_HI + off);
                ldsm_x4(al[mi], smb + OFF_A_LO + off);
            }
#pragma unroll
            for (int np = 0; np < 4; np++) {
                uint32_t bh[4], bl[4];
                int off = SW128((n0w + np * 16 + rowL) * 128 + ks * 32 + chalf * 16);
                ldsm_x4(bh, wb + off);
                ldsm_x4(bl, wb + 32768 + off);
#pragma unroll
                for (int mi = 0; mi < 4; mi++) {
                    float* cA = acc[mi][np * 2];
                    float* cB = acc[mi][np * 2 + 1];
                    mma_bf16(cA, ah[mi], bh[0], bh[2]);
                    mma_bf16(cB, ah[mi], bh[1], bh[3]);
                    mma_bf16(cA, ah[mi], bl[0], bl[2]);
                    mma_bf16(cB, ah[mi], bl[1], bl[3]);
                    mma_bf16(cA, al[mi], bh[0], bh[2]);
                    mma_bf16(cB, al[mi], bh[1], bh[3]);
                }
            }
        }
    }

    // ---------------- Phase 1 epilogue: bias, Y -> smem bf16 hi/lo, ||y||^2 ----------------
    __syncthreads();
    if (tid < 128) y2s[tid] = 0.f;
    __syncthreads();
#pragma unroll
    for (int mi = 0; mi < 4; mi++) {
#pragma unroll
        for (int rp = 0; rp < 2; rp++) {
            const int r = m0 + mi * 16 + g + rp * 8;
            float y2p = 0.f;
#pragma unroll
            for (int ni = 0; ni < 8; ni++) {
                const int e = n0w + ni * 8 + qc * 2;
                float v0 = acc[mi][ni][rp * 2 + 0] + __ldg(&bias[e]);
                float v1 = acc[mi][ni][rp * 2 + 1] + __ldg(&bias[e + 1]);
                y2p += v0 * v0 + v1 * v1;
                unsigned short h0, l0, h1, l1;
                f2bf(v0, h0, l0); f2bf(v1, h1, l1);
                const int off = SW128(r * 128 + (e & 63) * 2);
                const int cb = (e >> 6) * 16384;
                *(uint32_t*)(sm + OFF_Y_HI + cb + off) = (uint32_t)h0 | ((uint32_t)h1 << 16);
                *(uint32_t*)(sm + OFF_Y_LO + cb + off) = (uint32_t)l0 | ((uint32_t)l1 << 16);
            }
            y2p += __shfl_xor_sync(0xFFFFFFFFu, y2p, 1);
            y2p += __shfl_xor_sync(0xFFFFFFFFu, y2p, 2);
            if (qc == 0) atomicAdd(&y2s[r], y2p);
        }
    }

    // ================= Phase 2: screened distances (hi*hi only) =================
    float tv1[4][2], tv2[4][2];
    int   ti1[4][2], ti2[4][2];
#pragma unroll
    for (int mi = 0; mi < 4; mi++)
#pragma unroll
        for (int rp = 0; rp < 2; rp++) {
            tv1[mi][rp] = FLT_MAX; tv2[mi][rp] = FLT_MAX;
            ti1[mi][rp] = 0;       ti2[mi][rp] = 0;
        }

    prefetch_e(0); CP_COMMIT();

    for (int it = 0; it < 16; it++) {
        const int kt = it >> 2, ec = it & 3;
        CP_WAIT0();
        __syncthreads();
        if (it + 1 < 16) prefetch_e(it + 1);
        CP_COMMIT();

        if (ec == 0) {
#pragma unroll
            for (int mi = 0; mi < 4; mi++)
#pragma unroll
                for (int ni = 0; ni < 8; ni++)
#pragma unroll
                    for (int q = 0; q < 4; q++) acc[mi][ni][q] = 0.f;
        }

        const uint32_t eb = smb + OFF_EBUF + (it & 1) * 32768;
        const uint32_t yh = smb + OFF_Y_HI + ec * 16384;
#pragma unroll
        for (int ks = 0; ks < 4; ks++) {
            uint32_t ah[4][4];
#pragma unroll
            for (int mi = 0; mi < 4; mi++) {
                int off = SW128((m0 + mi * 16 + rowL) * 128 + ks * 32 + chalf * 16);
                ldsm_x4(ah[mi], yh + off);
            }
#pragma unroll
            for (int np = 0; np < 4; np++) {
                uint32_t bh[4];
                int off = SW128((n0w + np * 16 + rowL) * 128 + ks * 32 + chalf * 16);
                ldsm_x4(bh, eb + off);
#pragma unroll
                for (int mi = 0; mi < 4; mi++) {
                    mma_bf16(acc[mi][np * 2],     ah[mi], bh[0], bh[2]);
                    mma_bf16(acc[mi][np * 2 + 1], ah[mi], bh[1], bh[3]);
                }
            }
        }

        if (ec == 3) {
#pragma unroll
            for (int ni = 0; ni < 8; ni++) {
                const int k0 = kt * 256 + n0w + ni * 8 + qc * 2;
                const float e2a = __ldg(&g_e2[k0]);
                const float e2b = __ldg(&g_e2[k0 + 1]);
#pragma unroll
                for (int mi = 0; mi < 4; mi++) {
#pragma unroll
                    for (int rp = 0; rp < 2; rp++) {
                        float d0 = e2a - 2.0f * acc[mi][ni][rp * 2 + 0];
                        float d1 = e2b - 2.0f * acc[mi][ni][rp * 2 + 1];
                        if (d0 < tv1[mi][rp]) {
                            tv2[mi][rp] = tv1[mi][rp]; ti2[mi][rp] = ti1[mi][rp];
                            tv1[mi][rp] = d0;          ti1[mi][rp] = k0;
                        } else if (d0 < tv2[mi][rp]) { tv2[mi][rp] = d0; ti2[mi][rp] = k0; }
                        if (d1 < tv1[mi][rp]) {
                            tv2[mi][rp] = tv1[mi][rp]; ti2[mi][rp] = ti1[mi][rp];
                            tv1[mi][rp] = d1;          ti1[mi][rp] = k0 + 1;
                        } else if (d1 < tv2[mi][rp]) { tv2[mi][rp] = d1; ti2[mi][rp] = k0 + 1; }
                    }
                }
            }
        }
    }

    // ---------------- dump candidates to smem ----------------
    __syncthreads();                      // embed buffers dead; reuse for cand arrays
    float* cv = (float*)(sm + OFF_CV);
    int*   cx = (int*)  (sm + OFF_CI);
    const int slot = (wid >> 1) * 4 + qc;     // 0..15
#pragma unroll
    for (int mi = 0; mi < 4; mi++) {
#pragma unroll
        for (int rp = 0; rp < 2; rp++) {
            const int r = m0 + mi * 16 + g + rp * 8;
            cv[r * 32 + slot * 2 + 0] = tv1[mi][rp];
            cx[r * 32 + slot * 2 + 0] = ti1[mi][rp];
            cv[r * 32 + slot * 2 + 1] = tv2[mi][rp];
            cx[r * 32 + slot * 2 + 1] = ti2[mi][rp];
        }
    }
    __syncthreads();

    // ---------------- exact re-check: warp wid handles rows wid*16.. ----------------
    float wl = 0.f;
    for (int rr = 0; rr < 16; rr++) {
        const int r = wid * 16 + rr;
        float v = cv[r * 32 + lane];
        int   ix = cx[r * 32 + lane];
        // warp min (value, then idx asc)
        float mv = v; int mix = ix;
#pragma unroll
        for (int d = 16; d > 0; d >>= 1) {
            float ov = __shfl_xor_sync(0xFFFFFFFFu, mv, d);
            int   oi = __shfl_xor_sync(0xFFFFFFFFu, mix, d);
            if (ov < mv || (ov == mv && oi < mix)) { mv = ov; mix = oi; }
        }
        unsigned mask = __ballot_sync(0xFFFFFFFFu, v <= mv + MARGIN);
        float bd = FLT_MAX; int bi = 0x7FFFFFFF;
        const int e_base = lane * 8;
        const int cb = (e_base >> 6) * 16384;
        const int off = SW128((r & 127) * 128 + (e_base & 63) * 2);
        uint4 H = *(uint4*)(sm + OFF_Y_HI + cb + off);
        uint4 L = *(uint4*)(sm + OFF_Y_LO + cb + off);
        float yv[8];
        yv[0] = bf_lo(H.x) + bf_lo(L.x); yv[1] = bf_hi(H.x) + bf_hi(L.x);
        yv[2] = bf_lo(H.y) + bf_lo(L.y); yv[3] = bf_hi(H.y) + bf_hi(L.y);
        yv[4] = bf_lo(H.z) + bf_lo(L.z); yv[5] = bf_hi(H.z) + bf_hi(L.z);
        yv[6] = bf_lo(H.w) + bf_lo(L.w); yv[7] = bf_hi(H.w) + bf_hi(L.w);
        while (mask) {
            const int src = __ffs(mask) - 1;
            mask &= mask - 1;
            const int cidx = __shfl_sync(0xFFFFFFFFu, ix, src);
            const float4 ea = __ldg((const float4*)(embed + (size_t)cidx * EE + e_base));
            const float4 eb2 = __ldg((const float4*)(embed + (size_t)cidx * EE + e_base + 4));
            float p = yv[0] * ea.x + yv[1] * ea.y + yv[2] * ea.z + yv[3] * ea.w
                    + yv[4] * eb2.x + yv[5] * eb2.y + yv[6] * eb2.z + yv[7] * eb2.w;
#pragma unroll
            for (int d = 16; d > 0; d >>= 1) p += __shfl_xor_sync(0xFFFFFFFFu, p, d);
            const float dd = __ldg(&g_e2[cidx]) - 2.0f * p;
            if (dd < bd || (dd == bd && cidx < bi)) { bd = dd; bi = cidx; }
        }
        if (lane == 0) {
            g_idx[n0 + r] = bi;
            atomicAdd(&g_hist[bi], 1u);
            wl += bd + y2s[r];
        }
    }
    if (lane == 0) lred[wid] = wl;
    __syncthreads();
    if (tid == 0) {
        float s = 0.f;
#pragma unroll
        for (int wgi = 0; wgi < 8; wgi++) s += lred[wgi];
        atomicAdd(&g_loss, (double)s);
    }
}

// ---------------------------------------------------------------------------
__global__ void out_kernel(const float* __restrict__ embed, float* __restrict__ out) {
    __shared__ float tile[32][33];
    __shared__ int sidx[32];
    const int t0 = blockIdx.x * 32;
    const int b  = blockIdx.y;
    const int tx = threadIdx.x & 31;
    const int ty = threadIdx.x >> 5;
    if (threadIdx.x < 32) sidx[threadIdx.x] = g_idx[b * TT + t0 + threadIdx.x];
    __syncthreads();
    for (int e0 = 0; e0 < EE; e0 += 32) {
#pragma unroll
        for (int q = 0; q < 4; q++) {
            int t = ty * 4 + q;
            tile[t][tx] = embed[(size_t)sidx[t] * EE + e0 + tx];
        }
        __syncthreads();
#pragma unroll
        for (int q = 0; q < 4; q++) {
            int e = e0 + ty * 4 + q;
            out[((size_t)(b * EE + e)) * TT + t0 + tx] = tile[tx][ty * 4 + q];
        }
        __syncthreads();
    }
}

// ---------------------------------------------------------------------------
__global__ void finalize_kernel(float* __restrict__ out, int out_size) {
    __shared__ float red[8];
    const int tid = threadIdx.x;
    float s = 0.f;
    for (int k = tid; k < KK; k += 256) {
        float p = (float)g_hist[k] / (float)NN;
        s += p * logf(p + 1e-10f);
    }
#pragma unroll
    for (int off = 16; off > 0; off >>= 1) s += __shfl_down_sync(0xFFFFFFFFu, s, off);
    if ((tid & 31) == 0) red[tid >> 5] = s;
    __syncthreads();
    if (tid == 0) {
        float tot = 0.f;
#pragma unroll
        for (int wgi = 0; wgi < 8; wgi++) tot += red[wgi];
        const float log_perp = -tot;
        const float loss = 0.25f * (float)(g_loss / ((double)NN * (double)EE));
        const float kld = logf((float)KK) * (float)TT;
        const long long base = (long long)NN * EE;
        if (base + 0 < out_size) out[base + 0] = loss;
        for (int i = 0; i < BB; i++)
            if (base + 1 + i < out_size) out[base + 1 + i] = kld;
        if (base + 1 + BB < out_size) out[base + 1 + BB] = log_perp;
    }
}

// ---------------------------------------------------------------------------
extern "C" void kernel_launch(void* const* d_in, const int* in_sizes, int n_in,
                              void* d_out, int out_size) {
    const float* x     = (const float*)d_in[0];
    const float* w     = (const float*)d_in[1];
    const float* bias  = (const float*)d_in[2];
    const float* embed = (const float*)d_in[3];
    float* out = (float*)d_out;

    static int attr_set = 0;
    if (!attr_set) {
        cudaFuncSetAttribute(fused_kernel, cudaFuncAttributeMaxDynamicSharedMemorySize, SMEM_BYTES);
        attr_set = 1;
    }

    init_kernel<<<4, 256>>>(embed);
    prep_kernel<<<1024, 256>>>(w, embed);
    fused_kernel<<<NN / 128, 256, SMEM_BYTES>>>(x, bias, embed);
    out_kernel<<<dim3(TT / 32, BB), 256>>>(embed, out);
    finalize_kernel<<<1, 256>>>(out, out_size);
}

// round 10
// speedup vs baseline: 3.7149x; 1.0572x over previous
#include <cuda_runtime.h>
#include <cuda_bf16.h>
#include <math.h>
#include <float.h>
#include <stdint.h>

#define BB 16
#define CC 512
#define TT 4096
#define EE 256
#define KK 1024
#define NN (BB*TT)

// ---------------- dynamic smem layout (bytes) ----------------
#define OFF_STAGE  0                   // 64 x 132 fp32 = 33792 (phase1); out tile (phase3)
#define OFF_A_HI   34816               // 16384
#define OFF_A_LO   51200               // 16384
#define OFF_WBUF   67584               // 2 x (32768 hi + 32768 lo) = 131072 -> 198656
// Phase 2: Y hi/lo | embed hi double-buffers | candidates | reductions
#define OFF_Y_HI   0                   // 4 x 16384 = 65536
#define OFF_Y_LO   65536               // 65536
#define OFF_EBUF   131072              // 2 x 32768 (hi only) -> 196608
#define OFF_CV     131072              // cand values  [128][64] f32 = 32768 (after mma loop)
#define OFF_CI     163840              // cand indices [128][64] i32 = 32768
#define OFF_RED    196608              // y2s[128] f32
#define OFF_LRED   197120              // [16] f32
#define SMEM_BYTES 229376

#define STAGE_STR 132
#define MARGIN 4.0f

#define SW128(o) ((o) ^ (((o) >> 3) & 0x70))

static __device__ __forceinline__ uint32_t smem_u32(const void* p) {
    uint32_t a;
    asm("{ .reg .u64 t; cvta.to.shared.u64 t, %1; cvt.u32.u64 %0, t; }" : "=r"(a) : "l"(p));
    return a;
}

static __device__ __forceinline__ void cp16(uint32_t dst, const void* src) {
    asm volatile("cp.async.cg.shared.global [%0], [%1], 16;"
                 :: "r"(dst), "l"(__cvta_generic_to_global(src)));
}
#define CP_COMMIT() asm volatile("cp.async.commit_group;" ::: "memory")
#define CP_WAIT0()  asm volatile("cp.async.wait_group 0;" ::: "memory")

static __device__ __forceinline__ void ldsm_x4(uint32_t* r, uint32_t addr) {
    asm volatile("ldmatrix.sync.aligned.m8n8.x4.shared.b16 {%0,%1,%2,%3}, [%4];"
                 : "=r"(r[0]), "=r"(r[1]), "=r"(r[2]), "=r"(r[3]) : "r"(addr));
}

static __device__ __forceinline__ void mma_bf16(float* c, const uint32_t* a,
                                                uint32_t b0, uint32_t b1) {
    asm volatile(
        "mma.sync.aligned.m16n8k16.row.col.f32.bf16.bf16.f32 "
        "{%0,%1,%2,%3}, {%4,%5,%6,%7}, {%8,%9}, {%0,%1,%2,%3};"
        : "+f"(c[0]), "+f"(c[1]), "+f"(c[2]), "+f"(c[3])
        : "r"(a[0]), "r"(a[1]), "r"(a[2]), "r"(a[3]), "r"(b0), "r"(b1));
}

static __device__ __forceinline__ void f2bf(float v, unsigned short& h, unsigned short& l) {
    __nv_bfloat16 hb = __float2bfloat16(v);
    h = __bfloat16_as_ushort(hb);
    l = __bfloat16_as_ushort(__float2bfloat16(v - __bfloat162float(hb)));
}

static __device__ __forceinline__ float bf_hi(uint32_t w) {
    return __bfloat162float(__ushort_as_bfloat16((unsigned short)(w >> 16)));
}
static __device__ __forceinline__ float bf_lo(uint32_t w) {
    return __bfloat162float(__ushort_as_bfloat16((unsigned short)(w & 0xFFFF)));
}

// ---------------- global scratch ----------------
__device__ float        g_e2[KK];
__device__ unsigned int g_hist[KK];
__device__ double       g_loss;
__device__ uint4        g_wt4[2][8][2048];      // w:     [hi/lo][c-chunk][256e x 64c bf16, SW128]
__device__ uint4        g_et4[4][4][2048];      // embed hi: [k-chunk(256)][e-chunk][256k x 64e]

// ---------------------------------------------------------------------------
__global__ void init_kernel(const float* __restrict__ embed) {
    int k = blockIdx.x * blockDim.x + threadIdx.x;
    if (k < KK) {
        const float* row = embed + (size_t)k * EE;
        float s = 0.f;
#pragma unroll 8
        for (int e = 0; e < EE; e++) { float v = row[e]; s += v * v; }
        g_e2[k] = s;
        g_hist[k] = 0u;
    }
    if (k == 0) g_loss = 0.0;
}

// Convert w (hi/lo) and embed (hi only) into MMA-ready swizzled bf16 tiles.
__global__ void prep_kernel(const float* __restrict__ w, const float* __restrict__ embed) {
    int i = blockIdx.x * 256 + threadIdx.x;      // 0 .. 262143
    {   // embed[k][e]
        int k = i >> 8, e = i & 255;
        float v = embed[i];
        unsigned short h = __bfloat16_as_ushort(__float2bfloat16(v));
        int off = SW128((k & 255) * 128 + (e & 63) * 2);
        ((unsigned short*)g_et4[k >> 8][e >> 6])[off >> 1] = h;
    }
    if (i < 131072) {   // w[e][c]
        int e = i >> 9, c = i & 511;
        float v = w[i];
        unsigned short h, l; f2bf(v, h, l);
        int off = SW128(e * 128 + (c & 63) * 2);
        ((unsigned short*)g_wt4[0][c >> 6])[off >> 1] = h;
        ((unsigned short*)g_wt4[1][c >> 6])[off >> 1] = l;
    }
}

// ---------------------------------------------------------------------------
// Fused (512 threads, 16 warps): proj (3-term split) -> Y bf16 hi/lo smem ->
// screened distances (hi*hi) -> top-2 cands -> exact fp32 re-check ->
// loss/hist -> inline transposed output gather.
// Warp layout: m-split 2 (64 rows), n-split 8 (32 cols).
// ---------------------------------------------------------------------------
__global__ __launch_bounds__(512, 1)
void fused_kernel(const float* __restrict__ x, const float* __restrict__ bias,
                  const float* __restrict__ embed, float* __restrict__ out) {
    extern __shared__ char sm[];
    __shared__ int sidx[128];
    const int tid  = threadIdx.x;
    const int wid  = tid >> 5;
    const int lane = tid & 31;
    const uint32_t smb = smem_u32(sm);

    const int b  = blockIdx.x >> 5;
    const int t0 = (blockIdx.x & 31) * 128;

    const int m0   = (wid & 1) * 64;
    const int n0w  = (wid >> 1) * 32;     // 32-col slice
    const int g    = lane >> 2;
    const int qc   = lane & 3;
    const int rowL  = lane & 15;
    const int chalf = (lane >> 4);

    float* y2s  = (float*)(sm + OFF_RED);
    float* lred = (float*)(sm + OFF_LRED);
    float* stg  = (float*)(sm + OFF_STAGE);

    float acc[4][4][4];

    auto prefetch_x = [&](int ci) {
        const int c0 = ci * 64;
#pragma unroll
        for (int p = 0; p < 4; p++) {
            int cl = p * 16 + wid;
            cp16(smb + OFF_STAGE + (cl * STAGE_STR + lane * 4) * 4,
                 x + ((size_t)(b * CC + c0 + cl)) * TT + t0 + lane * 4);
        }
    };
    auto prefetch_w = [&](int ci) {
        const uint32_t base = smb + OFF_WBUF + (ci & 1) * 65536;
#pragma unroll
        for (int q = 0; q < 4; q++) {
            int idx = q * 512 + tid;
            cp16(base + idx * 16, &g_wt4[0][ci][idx]);
            cp16(base + 32768 + idx * 16, &g_wt4[1][ci][idx]);
        }
    };
    auto prefetch_e = [&](int it) {
        const int kt = it >> 2, ec = it & 3;
        const uint32_t base = smb + OFF_EBUF + (it & 1) * 32768;
#pragma unroll
        for (int q = 0; q < 4; q++) {
            int idx = q * 512 + tid;
            cp16(base + idx * 16, &g_et4[kt][ec][idx]);
        }
    };

    // ================= Phase 1: projection (3-term split) =================
#pragma unroll
    for (int mi = 0; mi < 4; mi++)
#pragma unroll
        for (int ni = 0; ni < 4; ni++)
#pragma unroll
            for (int q = 0; q < 4; q++) acc[mi][ni][q] = 0.f;

    prefetch_x(0); prefetch_w(0); CP_COMMIT();

    for (int ci = 0; ci < 8; ci++) {
        CP_WAIT0();
        __syncthreads();
        {   // transpose + split x -> A [t=128][c=64] bf16 hi/lo, swizzled
            const int r = tid >> 2;
            const int quarter = tid & 3;
#pragma unroll
            for (int i2 = 0; i2 < 8; i2++) {
                float v0 = stg[(quarter * 16 + 2 * i2 + 0) * STAGE_STR + r];
                float v1 = stg[(quarter * 16 + 2 * i2 + 1) * STAGE_STR + r];
                unsigned short h0, l0, h1, l1;
                f2bf(v0, h0, l0); f2bf(v1, h1, l1);
                int off = SW128(r * 128 + quarter * 32 + i2 * 4);
                *(uint32_t*)(sm + OFF_A_HI + off) = (uint32_t)h0 | ((uint32_t)h1 << 16);
                *(uint32_t*)(sm + OFF_A_LO + off) = (uint32_t)l0 | ((uint32_t)l1 << 16);
            }
        }
        __syncthreads();
        if (ci + 1 < 8) { prefetch_x(ci + 1); prefetch_w(ci + 1); }
        CP_COMMIT();

        const uint32_t wb = smb + OFF_WBUF + (ci & 1) * 65536;
#pragma unroll
        for (int ks = 0; ks < 4; ks++) {
            uint32_t ah[4][4], al[4][4];
#pragma unroll
            for (int mi = 0; mi < 4; mi++) {
                int off = SW128((m0 + mi * 16 + rowL) * 128 + ks * 32 + chalf * 16);
                ldsm_x4(ah[mi], smb + OFF_A_HI + off);
                ldsm_x4(al[mi], smb + OFF_A_LO + off);
            }
#pragma unroll
            for (int np = 0; np < 2; np++) {
                uint32_t bh[4], bl[4];
                int off = SW128((n0w + np * 16 + rowL) * 128 + ks * 32 + chalf * 16);
                ldsm_x4(bh, wb + off);
                ldsm_x4(bl, wb + 32768 + off);
#pragma unroll
                for (int mi = 0; mi < 4; mi++) {
                    float* cA = acc[mi][np * 2];
                    float* cB = acc[mi][np * 2 + 1];
                    mma_bf16(cA, ah[mi], bh[0], bh[2]);
                    mma_bf16(cB, ah[mi], bh[1], bh[3]);
                    mma_bf16(cA, ah[mi], bl[0], bl[2]);
                    mma_bf16(cB, ah[mi], bl[1], bl[3]);
                    mma_bf16(cA, al[mi], bh[0], bh[2]);
                    mma_bf16(cB, al[mi], bh[1], bh[3]);
                }
            }
        }
    }

    // ---------------- Phase 1 epilogue: bias, Y -> smem, ||y||^2 ----------------
    __syncthreads();
    if (tid < 128) y2s[tid] = 0.f;
    __syncthreads();
#pragma unroll
    for (int mi = 0; mi < 4; mi++) {
#pragma unroll
        for (int rp = 0; rp < 2; rp++) {
            const int r = m0 + mi * 16 + g + rp * 8;
            float y2p = 0.f;
#pragma unroll
            for (int ni = 0; ni < 4; ni++) {
                const int e = n0w + ni * 8 + qc * 2;
                float v0 = acc[mi][ni][rp * 2 + 0] + __ldg(&bias[e]);
                float v1 = acc[mi][ni][rp * 2 + 1] + __ldg(&bias[e + 1]);
                y2p += v0 * v0 + v1 * v1;
                unsigned short h0, l0, h1, l1;
                f2bf(v0, h0, l0); f2bf(v1, h1, l1);
                const int off = SW128(r * 128 + (e & 63) * 2);
                const int cb = (e >> 6) * 16384;
                *(uint32_t*)(sm + OFF_Y_HI + cb + off) = (uint32_t)h0 | ((uint32_t)h1 << 16);
                *(uint32_t*)(sm + OFF_Y_LO + cb + off) = (uint32_t)l0 | ((uint32_t)l1 << 16);
            }
            y2p += __shfl_xor_sync(0xFFFFFFFFu, y2p, 1);
            y2p += __shfl_xor_sync(0xFFFFFFFFu, y2p, 2);
            if (qc == 0) atomicAdd(&y2s[r], y2p);
        }
    }

    // ================= Phase 2: screened distances (hi*hi only) =================
    float tv1[4][2], tv2[4][2];
    int   ti1[4][2], ti2[4][2];
#pragma unroll
    for (int mi = 0; mi < 4; mi++)
#pragma unroll
        for (int rp = 0; rp < 2; rp++) {
            tv1[mi][rp] = FLT_MAX; tv2[mi][rp] = FLT_MAX;
            ti1[mi][rp] = 0;       ti2[mi][rp] = 0;
        }

    prefetch_e(0); CP_COMMIT();

    for (int it = 0; it < 16; it++) {
        const int kt = it >> 2, ec = it & 3;
        CP_WAIT0();
        __syncthreads();
        if (it + 1 < 16) prefetch_e(it + 1);
        CP_COMMIT();

        if (ec == 0) {
#pragma unroll
            for (int mi = 0; mi < 4; mi++)
#pragma unroll
                for (int ni = 0; ni < 4; ni++)
#pragma unroll
                    for (int q = 0; q < 4; q++) acc[mi][ni][q] = 0.f;
        }

        const uint32_t eb = smb + OFF_EBUF + (it & 1) * 32768;
        const uint32_t yh = smb + OFF_Y_HI + ec * 16384;
#pragma unroll
        for (int ks = 0; ks < 4; ks++) {
            uint32_t ah[4][4];
#pragma unroll
            for (int mi = 0; mi < 4; mi++) {
                int off = SW128((m0 + mi * 16 + rowL) * 128 + ks * 32 + chalf * 16);
                ldsm_x4(ah[mi], yh + off);
            }
#pragma unroll
            for (int np = 0; np < 2; np++) {
                uint32_t bh[4];
                int off = SW128((n0w + np * 16 + rowL) * 128 + ks * 32 + chalf * 16);
                ldsm_x4(bh, eb + off);
#pragma unroll
                for (int mi = 0; mi < 4; mi++) {
                    mma_bf16(acc[mi][np * 2],     ah[mi], bh[0], bh[2]);
                    mma_bf16(acc[mi][np * 2 + 1], ah[mi], bh[1], bh[3]);
                }
            }
        }

        if (ec == 3) {
#pragma unroll
            for (int ni = 0; ni < 4; ni++) {
                const int k0 = kt * 256 + n0w + ni * 8 + qc * 2;
                const float e2a = __ldg(&g_e2[k0]);
                const float e2b = __ldg(&g_e2[k0 + 1]);
#pragma unroll
                for (int mi = 0; mi < 4; mi++) {
#pragma unroll
                    for (int rp = 0; rp < 2; rp++) {
                        float d0 = e2a - 2.0f * acc[mi][ni][rp * 2 + 0];
                        float d1 = e2b - 2.0f * acc[mi][ni][rp * 2 + 1];
                        if (d0 < tv1[mi][rp]) {
                            tv2[mi][rp] = tv1[mi][rp]; ti2[mi][rp] = ti1[mi][rp];
                            tv1[mi][rp] = d0;          ti1[mi][rp] = k0;
                        } else if (d0 < tv2[mi][rp]) { tv2[mi][rp] = d0; ti2[mi][rp] = k0; }
                        if (d1 < tv1[mi][rp]) {
                            tv2[mi][rp] = tv1[mi][rp]; ti2[mi][rp] = ti1[mi][rp];
                            tv1[mi][rp] = d1;          ti1[mi][rp] = k0 + 1;
                        } else if (d1 < tv2[mi][rp]) { tv2[mi][rp] = d1; ti2[mi][rp] = k0 + 1; }
                    }
                }
            }
        }
    }

    // ---------------- dump candidates (64 per row) ----------------
    __syncthreads();                      // embed buffers dead
    float* cv = (float*)(sm + OFF_CV);
    int*   cx = (int*)  (sm + OFF_CI);
    const int slot = (wid >> 1) * 4 + qc;     // 0..31
#pragma unroll
    for (int mi = 0; mi < 4; mi++) {
#pragma unroll
        for (int rp = 0; rp < 2; rp++) {
            const int r = m0 + mi * 16 + g + rp * 8;
            cv[r * 64 + slot * 2 + 0] = tv1[mi][rp];
            cx[r * 64 + slot * 2 + 0] = ti1[mi][rp];
            cv[r * 64 + slot * 2 + 1] = tv2[mi][rp];
            cx[r * 64 + slot * 2 + 1] = ti2[mi][rp];
        }
    }
    __syncthreads();

    // ---------------- exact re-check: warp wid -> rows wid*8.. ----------------
    float wl = 0.f;
    for (int rr = 0; rr < 8; rr++) {
        const int r = wid * 8 + rr;
        float v0 = cv[r * 64 + lane];
        int   i0 = cx[r * 64 + lane];
        float v1 = cv[r * 64 + 32 + lane];
        int   i1 = cx[r * 64 + 32 + lane];
        float mv = fminf(v0, v1);
#pragma unroll
        for (int d = 16; d > 0; d >>= 1)
            mv = fminf(mv, __shfl_xor_sync(0xFFFFFFFFu, mv, d));
        unsigned mask0 = __ballot_sync(0xFFFFFFFFu, v0 <= mv + MARGIN);
        unsigned mask1 = __ballot_sync(0xFFFFFFFFu, v1 <= mv + MARGIN);
        float bd = FLT_MAX; int bi = 0x7FFFFFFF;
        const int e_base = lane * 8;
        const int cb = (e_base >> 6) * 16384;
        const int off = SW128(r * 128 + (e_base & 63) * 2);
        uint4 H = *(uint4*)(sm + OFF_Y_HI + cb + off);
        uint4 L = *(uint4*)(sm + OFF_Y_LO + cb + off);
        float yv[8];
        yv[0] = bf_lo(H.x) + bf_lo(L.x); yv[1] = bf_hi(H.x) + bf_hi(L.x);
        yv[2] = bf_lo(H.y) + bf_lo(L.y); yv[3] = bf_hi(H.y) + bf_hi(L.y);
        yv[4] = bf_lo(H.z) + bf_lo(L.z); yv[5] = bf_hi(H.z) + bf_hi(L.z);
        yv[6] = bf_lo(H.w) + bf_lo(L.w); yv[7] = bf_hi(H.w) + bf_hi(L.w);
#pragma unroll
        for (int half = 0; half < 2; half++) {
            unsigned mask = half ? mask1 : mask0;
            while (mask) {
                const int src = __ffs(mask) - 1;
                mask &= mask - 1;
                const int cidx = __shfl_sync(0xFFFFFFFFu, half ? i1 : i0, src);
                const float4 ea = __ldg((const float4*)(embed + (size_t)cidx * EE + e_base));
                const float4 eb2 = __ldg((const float4*)(embed + (size_t)cidx * EE + e_base + 4));
                float p = yv[0] * ea.x + yv[1] * ea.y + yv[2] * ea.z + yv[3] * ea.w
                        + yv[4] * eb2.x + yv[5] * eb2.y + yv[6] * eb2.z + yv[7] * eb2.w;
#pragma unroll
                for (int d = 16; d > 0; d >>= 1) p += __shfl_xor_sync(0xFFFFFFFFu, p, d);
                const float dd = __ldg(&g_e2[cidx]) - 2.0f * p;
                if (dd < bd || (dd == bd && cidx < bi)) { bd = dd; bi = cidx; }
            }
        }
        if (lane == 0) {
            sidx[r] = bi;
            atomicAdd(&g_hist[bi], 1u);
            wl += bd + y2s[r];
        }
    }
    if (lane == 0) lred[wid] = wl;
    __syncthreads();
    if (tid == 0) {
        float s = 0.f;
#pragma unroll
        for (int wgi = 0; wgi < 16; wgi++) s += lred[wgi];
        atomicAdd(&g_loss, (double)s);
    }

    // ---------------- Phase 3: inline transposed output ----------------
    // out[b, e, t0 + r] = embed[sidx[r], e]
    float* tile = (float*)(sm + OFF_STAGE);   // [128][33]
    const int r3 = tid & 127;
    const int eg = tid >> 7;                  // 0..3
    for (int e0 = 0; e0 < EE; e0 += 32) {
        __syncthreads();
        {
            const float4 ea = __ldg((const float4*)(embed + (size_t)sidx[r3] * EE + e0 + eg * 8));
            const float4 eb2 = __ldg((const float4*)(embed + (size_t)sidx[r3] * EE + e0 + eg * 8 + 4));
            float* tp = tile + r3 * 33 + eg * 8;
            tp[0] = ea.x; tp[1] = ea.y; tp[2] = ea.z; tp[3] = ea.w;
            tp[4] = eb2.x; tp[5] = eb2.y; tp[6] = eb2.z; tp[7] = eb2.w;
        }
        __syncthreads();
#pragma unroll
        for (int j = 0; j < 8; j++) {
            const int e = e0 + eg * 8 + j;
            out[((size_t)(b * EE + e)) * TT + t0 + r3] = tile[r3 * 33 + eg * 8 + j];
        }
    }
}

// ---------------------------------------------------------------------------
__global__ void finalize_kernel(float* __restrict__ out, int out_size) {
    __shared__ float red[8];
    const int tid = threadIdx.x;
    float s = 0.f;
    for (int k = tid; k < KK; k += 256) {
        float p = (float)g_hist[k] / (float)NN;
        s += p * logf(p + 1e-10f);
    }
#pragma unroll
    for (int off = 16; off > 0; off >>= 1) s += __shfl_down_sync(0xFFFFFFFFu, s, off);
    if ((tid & 31) == 0) red[tid >> 5] = s;
    __syncthreads();
    if (tid == 0) {
        float tot = 0.f;
#pragma unroll
        for (int wgi = 0; wgi < 8; wgi++) tot += red[wgi];
        const float log_perp = -tot;
        const float loss = 0.25f * (float)(g_loss / ((double)NN * (double)EE));
        const float kld = logf((float)KK) * (float)TT;
        const long long base = (long long)NN * EE;
        if (base + 0 < out_size) out[base + 0] = loss;
        for (int i = 0; i < BB; i++)
            if (base + 1 + i < out_size) out[base + 1 + i] = kld;
        if (base + 1 + BB < out_size) out[base + 1 + BB] = log_perp;
    }
}

// ---------------------------------------------------------------------------
extern "C" void kernel_launch(void* const* d_in, const int* in_sizes, int n_in,
                              void* d_out, int out_size) {
    const float* x     = (const float*)d_in[0];
    const float* w     = (const float*)d_in[1];
    const float* bias  = (const float*)d_in[2];
    const float* embed = (const float*)d_in[3];
    float* out = (float*)d_out;

    static int attr_set = 0;
    if (!attr_set) {
        cudaFuncSetAttribute(fused_kernel, cudaFuncAttributeMaxDynamicSharedMemorySize, SMEM_BYTES);
        attr_set = 1;
    }

    init_kernel<<<4, 256>>>(embed);
    prep_kernel<<<1024, 256>>>(w, embed);
    fused_kernel<<<NN / 128, 512, SMEM_BYTES>>>(x, bias, embed, out);
    finalize_kernel<<<1, 256>>>(out, out_size);
}